// round 4
// baseline (speedup 1.0000x reference)
#include <cuda_runtime.h>
#include <cuda_bf16.h>
#include <cstdint>

// Problem constants (fixed by the dataset)
#define NN 100000
#define NE 1600000

// ---------------- device scratch (allocation-free; ONLY touched from device code) ----------------
__device__ int   g_degi[NN];
__device__ int   g_rowptr[NN + 1];
__device__ int   g_cursor[NN];
__device__ int   g_adj[NE];
__device__ __align__(16) float g_invdeg[NN];
__device__ __align__(16) float g_agg[(size_t)NN * 256];
__device__ __align__(16) float g_h1[(size_t)NN * 256];
__device__ __align__(16) float g_h2[(size_t)NN * 256];

// Buffer selectors: 0 = external pointer (kernel arg), 1 = g_h1, 2 = g_h2
__device__ __forceinline__ const float* sel_cbuf(int sel, const float* ext) {
    if (sel == 1) return g_h1;
    if (sel == 2) return g_h2;
    return ext;
}
__device__ __forceinline__ float* sel_buf(int sel, float* ext) {
    if (sel == 1) return g_h1;
    if (sel == 2) return g_h2;
    return ext;
}

// ---------------- helpers ----------------
__device__ __forceinline__ float4 f4add(float4 a, float4 b) {
    a.x += b.x; a.y += b.y; a.z += b.z; a.w += b.w; return a;
}
__device__ __forceinline__ float4 f4scale(float4 a, float s) {
    a.x *= s; a.y *= s; a.z *= s; a.w *= s; return a;
}

// ---------------- CSR build ----------------
__global__ void zero_deg_kernel(int n) {
    int i = blockIdx.x * blockDim.x + threadIdx.x;
    if (i < n) g_degi[i] = 0;
}

// dst indices are int32 (JAX x64 is disabled; harness dtypes are f32/i32/bf16).
__global__ void hist_kernel(const int* __restrict__ dst, int E, int n) {
    int i = blockIdx.x * blockDim.x + threadIdx.x;
    int stride = gridDim.x * blockDim.x;
    for (; i < E; i += stride) {
        int d = dst[i];
        if ((unsigned)d < (unsigned)n)          // guard: never form a wild address
            atomicAdd(&g_degi[d], 1);
    }
}

__global__ void scan_kernel(int n) {
    __shared__ int warp_sums[32];
    __shared__ int s_carry;
    int tid = threadIdx.x, lane = tid & 31, wid = tid >> 5;
    if (tid == 0) s_carry = 0;
    __syncthreads();
    for (int base = 0; base < n; base += 1024) {
        int i = base + tid;
        int v = (i < n) ? g_degi[i] : 0;
        int s = v;
        #pragma unroll
        for (int off = 1; off < 32; off <<= 1) {
            int t = __shfl_up_sync(0xffffffffu, s, off);
            if (lane >= off) s += t;
        }
        if (lane == 31) warp_sums[wid] = s;
        __syncthreads();
        if (wid == 0) {
            int t2 = warp_sums[lane];
            #pragma unroll
            for (int off = 1; off < 32; off <<= 1) {
                int t = __shfl_up_sync(0xffffffffu, t2, off);
                if (lane >= off) t2 += t;
            }
            warp_sums[lane] = t2;  // inclusive warp totals
        }
        __syncthreads();
        int warp_off = (wid > 0) ? warp_sums[wid - 1] : 0;
        int incl = s + warp_off;
        int carry = s_carry;
        int excl = carry + incl - v;
        if (i < n) { g_rowptr[i] = excl; g_cursor[i] = excl; }
        __syncthreads();  // everyone has consumed s_carry / warp_sums
        if (tid == 1023) s_carry = carry + warp_sums[31];
        __syncthreads();
    }
    if (threadIdx.x == 0) g_rowptr[n] = s_carry;
}

__global__ void fill_kernel(const int* __restrict__ src, const int* __restrict__ dst,
                            int E, int n) {
    int i = blockIdx.x * blockDim.x + threadIdx.x;
    int stride = gridDim.x * blockDim.x;
    for (; i < E; i += stride) {
        int d = dst[i];
        int s = src[i];
        if ((unsigned)d < (unsigned)n && (unsigned)s < (unsigned)n) {
            int slot = atomicAdd(&g_cursor[d], 1);
            if ((unsigned)slot < (unsigned)NE) g_adj[slot] = s;
        }
    }
}

__global__ void invdeg_kernel(int n) {
    int i = blockIdx.x * blockDim.x + threadIdx.x;
    if (i < n) {
        float d = (float)g_degi[i];
        g_invdeg[i] = 1.0f / fmaxf(d, 1.0f);
    }
}

// ---------------- mean aggregation (CSR gather, warp per node) ----------------
// Reads feat (selector), writes g_agg.
template <int D>
__global__ void __launch_bounds__(256) aggregate_kernel(
    const float* __restrict__ ext, int src_sel, int n) {
    const float* feat = sel_cbuf(src_sel, ext);
    int w = (blockIdx.x * blockDim.x + threadIdx.x) >> 5;
    int lane = threadIdx.x & 31;
    if (w >= n) return;
    int start = g_rowptr[w];
    int end   = g_rowptr[w + 1];
    constexpr int C = D / 128;  // float4 chunks per lane (1 for D=128, 2 for D=256)
    float4 acc[C];
    #pragma unroll
    for (int c = 0; c < C; c++) acc[c] = make_float4(0.f, 0.f, 0.f, 0.f);
    for (int j = start; j < end; j++) {
        int s = g_adj[j];
        if ((unsigned)s >= (unsigned)n) continue;   // guard
        const float4* xs = (const float4*)(feat + (size_t)s * D);
        #pragma unroll
        for (int c = 0; c < C; c++) acc[c] = f4add(acc[c], xs[lane + 32 * c]);
    }
    float sc = g_invdeg[w];
    float4* o = (float4*)(g_agg + (size_t)w * D);
    #pragma unroll
    for (int c = 0; c < C; c++) o[lane + 32 * c] = f4scale(acc[c], sc);
}

// ---------------- dual-source SGEMM ----------------
// out[M,N] = act( g_agg @ Wl + X @ Wr + b ),  g_agg/X: [M,K] row-major, W: [K,N] row-major.
// Treated as A' = [g_agg | X] (M x 2K) @ [Wl ; Wr] (2K x N).
template <int K, int N, bool RELU>
__global__ void __launch_bounds__(256) gemm_dual(
    const float* __restrict__ x_ext, int x_sel,
    const float* __restrict__ Wl, const float* __restrict__ Wr,
    const float* __restrict__ bias,
    float* __restrict__ out_ext, int out_sel, int M) {
    const float* Ax = sel_cbuf(x_sel, x_ext);
    float* out = sel_buf(out_sel, out_ext);

    constexpr int BM = 128, BN = 128, BK = 8;
    __shared__ float As[BK][BM];
    __shared__ float Bs[BK][BN];

    int bm = blockIdx.x * BM;
    int bn = blockIdx.y * BN;
    int tid = threadIdx.x;

    int arow  = tid >> 1;         // 0..127
    int acol4 = (tid & 1) * 4;    // 0 or 4
    int brow  = tid >> 5;         // 0..7
    int bcol4 = (tid & 31) * 4;   // 0..124
    int tx = tid & 15, ty = tid >> 4;

    float acc[8][8];
    #pragma unroll
    for (int i = 0; i < 8; i++)
        #pragma unroll
        for (int j = 0; j < 8; j++) acc[i][j] = 0.f;

    #pragma unroll 1
    for (int k0 = 0; k0 < 2 * K; k0 += BK) {
        // ---- load A tile ----
        const float* A = (k0 < K) ? g_agg : Ax;
        int kk = (k0 < K) ? k0 : (k0 - K);
        int gm = bm + arow;
        float4 av = make_float4(0.f, 0.f, 0.f, 0.f);
        if (gm < M) av = *(const float4*)(A + (size_t)gm * K + kk + acol4);
        As[acol4 + 0][arow] = av.x;
        As[acol4 + 1][arow] = av.y;
        As[acol4 + 2][arow] = av.z;
        As[acol4 + 3][arow] = av.w;
        // ---- load B tile ----
        const float* W = (k0 < K) ? Wl : Wr;
        float4 bv = *(const float4*)(W + (size_t)(kk + brow) * N + bn + bcol4);
        *(float4*)&Bs[brow][bcol4] = bv;
        __syncthreads();

        #pragma unroll
        for (int k = 0; k < BK; k++) {
            float4 a0 = *(const float4*)&As[k][ty * 8];
            float4 a1 = *(const float4*)&As[k][ty * 8 + 4];
            float4 b0 = *(const float4*)&Bs[k][tx * 8];
            float4 b1 = *(const float4*)&Bs[k][tx * 8 + 4];
            float ar[8] = {a0.x, a0.y, a0.z, a0.w, a1.x, a1.y, a1.z, a1.w};
            float br[8] = {b0.x, b0.y, b0.z, b0.w, b1.x, b1.y, b1.z, b1.w};
            #pragma unroll
            for (int i = 0; i < 8; i++)
                #pragma unroll
                for (int j = 0; j < 8; j++) acc[i][j] += ar[i] * br[j];
        }
        __syncthreads();
    }

    // ---- epilogue ----
    #pragma unroll
    for (int i = 0; i < 8; i++) {
        int row = bm + ty * 8 + i;
        if (row >= M) continue;
        int col = bn + tx * 8;
        float4 v0, v1;
        v0.x = acc[i][0] + bias[col + 0];
        v0.y = acc[i][1] + bias[col + 1];
        v0.z = acc[i][2] + bias[col + 2];
        v0.w = acc[i][3] + bias[col + 3];
        v1.x = acc[i][4] + bias[col + 4];
        v1.y = acc[i][5] + bias[col + 5];
        v1.z = acc[i][6] + bias[col + 6];
        v1.w = acc[i][7] + bias[col + 7];
        if (RELU) {
            v0.x = fmaxf(v0.x, 0.f); v0.y = fmaxf(v0.y, 0.f);
            v0.z = fmaxf(v0.z, 0.f); v0.w = fmaxf(v0.w, 0.f);
            v1.x = fmaxf(v1.x, 0.f); v1.y = fmaxf(v1.y, 0.f);
            v1.z = fmaxf(v1.z, 0.f); v1.w = fmaxf(v1.w, 0.f);
        }
        *(float4*)(out + (size_t)row * N + col)     = v0;
        *(float4*)(out + (size_t)row * N + col + 4) = v1;
    }
}

// ---------------- launch ----------------
extern "C" void kernel_launch(void* const* d_in, const int* in_sizes, int n_in,
                              void* d_out, int out_size) {
    const float* x   = (const float*)d_in[0];
    const int*   ei  = (const int*)d_in[1];     // int32 edge_index [2, E] row-major
    const float* Wl0 = (const float*)d_in[2];
    const float* b0  = (const float*)d_in[3];
    const float* Wr0 = (const float*)d_in[4];
    const float* Wl1 = (const float*)d_in[5];
    const float* b1  = (const float*)d_in[6];
    const float* Wr1 = (const float*)d_in[7];
    const float* Wl2 = (const float*)d_in[8];
    const float* b2  = (const float*)d_in[9];
    const float* Wr2 = (const float*)d_in[10];
    float* out = (float*)d_out;

    const int E = in_sizes[1] / 2;
    const int M = in_sizes[0] / 128;
    const int* src = ei;          // row 0
    const int* dst = ei + E;      // row 1

    // --- CSR build (reused by all 3 layers) ---
    zero_deg_kernel<<<(M + 255) / 256, 256>>>(M);
    hist_kernel<<<2048, 256>>>(dst, E, M);
    scan_kernel<<<1, 1024>>>(M);
    fill_kernel<<<2048, 256>>>(src, dst, E, M);
    invdeg_kernel<<<(M + 255) / 256, 256>>>(M);

    const int agg_blocks = (M * 32 + 255) / 256;
    dim3 g2((M + 127) / 128, 2), g1((M + 127) / 128, 1);

    // --- layer 0: 128 -> 256, relu.  agg(x) ; h1 = relu([agg|x] @ [Wl0;Wr0] + b0)
    aggregate_kernel<128><<<agg_blocks, 256>>>(x, /*src_sel=*/0, M);
    gemm_dual<128, 256, true><<<g2, 256>>>(x, /*x_sel=*/0, Wl0, Wr0, b0,
                                           nullptr, /*out_sel=*/1, M);

    // --- layer 1: 256 -> 256, relu.  agg(h1) ; h2 = relu([agg|h1] @ [Wl1;Wr1] + b1)
    aggregate_kernel<256><<<agg_blocks, 256>>>(nullptr, /*src_sel=*/1, M);
    gemm_dual<256, 256, true><<<g2, 256>>>(nullptr, /*x_sel=*/1, Wl1, Wr1, b1,
                                           nullptr, /*out_sel=*/2, M);

    // --- layer 2: 256 -> 128, no act.  agg(h2) ; out = [agg|h2] @ [Wl2;Wr2] + b2
    aggregate_kernel<256><<<agg_blocks, 256>>>(nullptr, /*src_sel=*/2, M);
    gemm_dual<256, 128, false><<<g1, 256>>>(nullptr, /*x_sel=*/2, Wl2, Wr2, b2,
                                            out, /*out_sel=*/0, M);
}

// round 6
// speedup vs baseline: 1.7500x; 1.7500x over previous
#include <cuda_runtime.h>
#include <cuda_bf16.h>
#include <cstdint>

#define NN 100000
#define NE 1600000

// ---------------- device scratch (allocation-free; ONLY touched from device code) ----------------
__device__ int   g_degi[NN];
__device__ int   g_rowptr[NN + 1];
__device__ int   g_cursor[NN];
__device__ int   g_adj[NE];
__device__ __align__(16) float g_invdeg[NN];
__device__ __align__(16) float g_agg[(size_t)NN * 256];
__device__ __align__(16) float g_h1[(size_t)NN * 256];
__device__ __align__(16) float g_h2[(size_t)NN * 256];
// split bf16 weights, per layer: Whi[N][2K] then Wlo[N][2K] (rows k-contiguous)
// L0 @0 (2*65536), L1 @131072 (2*131072), L2 @393216 (2*65536) -> total 524288
__device__ __align__(16) __nv_bfloat16 g_wb[524288];

// Buffer selectors: 0 = external pointer (kernel arg), 1 = g_h1, 2 = g_h2
__device__ __forceinline__ const float* sel_cbuf(int sel, const float* ext) {
    if (sel == 1) return g_h1;
    if (sel == 2) return g_h2;
    return ext;
}
__device__ __forceinline__ float* sel_buf(int sel, float* ext) {
    if (sel == 1) return g_h1;
    if (sel == 2) return g_h2;
    return ext;
}

// ---------------- helpers ----------------
__device__ __forceinline__ float4 f4add(float4 a, float4 b) {
    a.x += b.x; a.y += b.y; a.z += b.z; a.w += b.w; return a;
}
__device__ __forceinline__ float4 f4scale(float4 a, float s) {
    a.x *= s; a.y *= s; a.z *= s; a.w *= s; return a;
}
__device__ __forceinline__ void split2(float a, float b, uint32_t& hi, uint32_t& lo) {
    __nv_bfloat16 ha = __float2bfloat16(a), hb = __float2bfloat16(b);
    float la = a - __bfloat162float(ha), lb = b - __bfloat162float(hb);
    __nv_bfloat162 th; th.x = ha; th.y = hb;
    __nv_bfloat162 tl; tl.x = __float2bfloat16(la); tl.y = __float2bfloat16(lb);
    hi = *reinterpret_cast<uint32_t*>(&th);
    lo = *reinterpret_cast<uint32_t*>(&tl);
}
__device__ __forceinline__ uint32_t smem_u32(const void* p) {
    uint32_t r;
    asm("{ .reg .u64 t; cvta.to.shared.u64 t, %1; cvt.u32.u64 %0, t; }" : "=r"(r) : "l"(p));
    return r;
}
__device__ __forceinline__ void ldmx4(uint32_t* r, uint32_t addr) {
    asm volatile("ldmatrix.sync.aligned.m8n8.x4.shared.b16 {%0,%1,%2,%3}, [%4];"
                 : "=r"(r[0]), "=r"(r[1]), "=r"(r[2]), "=r"(r[3]) : "r"(addr));
}
__device__ __forceinline__ void mma16816(float* c, const uint32_t* a, uint32_t b0, uint32_t b1) {
    asm volatile("mma.sync.aligned.m16n8k16.row.col.f32.bf16.bf16.f32 "
                 "{%0,%1,%2,%3}, {%4,%5,%6,%7}, {%8,%9}, {%0,%1,%2,%3};"
                 : "+f"(c[0]), "+f"(c[1]), "+f"(c[2]), "+f"(c[3])
                 : "r"(a[0]), "r"(a[1]), "r"(a[2]), "r"(a[3]), "r"(b0), "r"(b1));
}

// ---------------- CSR build ----------------
__global__ void zero_deg_kernel(int n) {
    int i = blockIdx.x * blockDim.x + threadIdx.x;
    if (i < n) g_degi[i] = 0;
}
__global__ void hist_kernel(const int* __restrict__ dst, int E, int n) {
    int i = blockIdx.x * blockDim.x + threadIdx.x;
    int stride = gridDim.x * blockDim.x;
    for (; i < E; i += stride) {
        int d = dst[i];
        if ((unsigned)d < (unsigned)n) atomicAdd(&g_degi[d], 1);
    }
}
__global__ void scan_kernel(int n) {
    __shared__ int warp_sums[32];
    __shared__ int s_carry;
    int tid = threadIdx.x, lane = tid & 31, wid = tid >> 5;
    if (tid == 0) s_carry = 0;
    __syncthreads();
    for (int base = 0; base < n; base += 1024) {
        int i = base + tid;
        int v = (i < n) ? g_degi[i] : 0;
        int s = v;
        #pragma unroll
        for (int off = 1; off < 32; off <<= 1) {
            int t = __shfl_up_sync(0xffffffffu, s, off);
            if (lane >= off) s += t;
        }
        if (lane == 31) warp_sums[wid] = s;
        __syncthreads();
        if (wid == 0) {
            int t2 = warp_sums[lane];
            #pragma unroll
            for (int off = 1; off < 32; off <<= 1) {
                int t = __shfl_up_sync(0xffffffffu, t2, off);
                if (lane >= off) t2 += t;
            }
            warp_sums[lane] = t2;
        }
        __syncthreads();
        int warp_off = (wid > 0) ? warp_sums[wid - 1] : 0;
        int incl = s + warp_off;
        int carry = s_carry;
        int excl = carry + incl - v;
        if (i < n) { g_rowptr[i] = excl; g_cursor[i] = excl; }
        __syncthreads();
        if (tid == 1023) s_carry = carry + warp_sums[31];
        __syncthreads();
    }
    if (threadIdx.x == 0) g_rowptr[n] = s_carry;
}
__global__ void fill_kernel(const int* __restrict__ src, const int* __restrict__ dst, int E, int n) {
    int i = blockIdx.x * blockDim.x + threadIdx.x;
    int stride = gridDim.x * blockDim.x;
    for (; i < E; i += stride) {
        int d = dst[i], s = src[i];
        if ((unsigned)d < (unsigned)n && (unsigned)s < (unsigned)n) {
            int slot = atomicAdd(&g_cursor[d], 1);
            if ((unsigned)slot < (unsigned)NE) g_adj[slot] = s;
        }
    }
}
__global__ void invdeg_kernel(int n) {
    int i = blockIdx.x * blockDim.x + threadIdx.x;
    if (i < n) g_invdeg[i] = 1.0f / fmaxf((float)g_degi[i], 1.0f);
}

// ---------------- weight prep: split fp32 W -> bf16 Whi/Wlo, k-contiguous rows ----------------
// Wl [K][N], Wr [K][N] column n. Output row n, col k in [0,2K): k<K -> Wl, else Wr.
__global__ void prep_w(const float* __restrict__ Wl, const float* __restrict__ Wr,
                       int K, int N, int off) {
    int K2 = 2 * K;
    int total = N * K2;
    for (int i = blockIdx.x * blockDim.x + threadIdx.x; i < total; i += gridDim.x * blockDim.x) {
        int n = i / K2, k = i % K2;
        float w = (k < K) ? Wl[(size_t)k * N + n] : Wr[(size_t)(k - K) * N + n];
        __nv_bfloat16 hi = __float2bfloat16(w);
        __nv_bfloat16 lo = __float2bfloat16(w - __bfloat162float(hi));
        g_wb[(size_t)off + (size_t)n * K2 + k] = hi;
        g_wb[(size_t)off + (size_t)N * K2 + (size_t)n * K2 + k] = lo;
    }
}

// ---------------- mean aggregation (CSR gather, warp per node) — proven in R4 ----------------
template <int D>
__global__ void __launch_bounds__(256) aggregate_kernel(
    const float* __restrict__ ext, int src_sel, int n) {
    const float* feat = sel_cbuf(src_sel, ext);
    int w = (blockIdx.x * blockDim.x + threadIdx.x) >> 5;
    int lane = threadIdx.x & 31;
    if (w >= n) return;
    int start = g_rowptr[w];
    int end   = g_rowptr[w + 1];
    constexpr int C = D / 128;
    float4 acc[C];
    #pragma unroll
    for (int c = 0; c < C; c++) acc[c] = make_float4(0.f, 0.f, 0.f, 0.f);
    for (int j = start; j < end; j++) {
        int s = g_adj[j];
        if ((unsigned)s >= (unsigned)n) continue;
        const float4* xs = (const float4*)(feat + (size_t)s * D);
        #pragma unroll
        for (int c = 0; c < C; c++) acc[c] = f4add(acc[c], xs[lane + 32 * c]);
    }
    float sc = g_invdeg[w];
    float4* o = (float4*)(g_agg + (size_t)w * D);
    #pragma unroll
    for (int c = 0; c < C; c++) o[lane + 32 * c] = f4scale(acc[c], sc);
}

// ---------------- tensor-core dual GEMM with on-the-fly split ----------------
// out[M,N] = act( [g_agg | X] @ Wsplit + b ), computed as Ahi@Whi + Ahi@Wlo + Alo@Whi.
// A fp32 [M][K] x2 sources; W bf16 in g_wb: Whi[N][2K] then Wlo[N][2K].
// BM=128, BN=128, BK=32; 8 warps of 32x64; m16n8k16 bf16 MMA via ldmatrix.
template <int K2, int N, bool RELU>
__global__ void __launch_bounds__(256) gemm_mma(
    const float* __restrict__ x_ext, int x_sel,
    const float* __restrict__ bias,
    float* __restrict__ out_ext, int out_sel,
    int wboff, int M) {
    // padded smem: row stride 40 bf16 (80B) -> conflict-free ldmatrix
    __shared__ __nv_bfloat16 sAh[128 * 40];
    __shared__ __nv_bfloat16 sAl[128 * 40];
    __shared__ __nv_bfloat16 sBh[128 * 40];
    __shared__ __nv_bfloat16 sBl[128 * 40];

    const float* Ax = sel_cbuf(x_sel, x_ext);
    float* out = sel_buf(out_sel, out_ext);
    constexpr int K = K2 / 2;
    constexpr int CHUNKS = K2 / 32;

    int tid = threadIdx.x;
    int wid = tid >> 5, lane = tid & 31;
    int bm = blockIdx.x * 128, bn = blockIdx.y * 128;
    int wm = (wid & 3) * 32;     // warp m offset
    int wn = (wid >> 2) * 64;    // warp n offset

    float acc[2][8][4];
    #pragma unroll
    for (int i = 0; i < 2; i++)
        #pragma unroll
        for (int j = 0; j < 8; j++)
            #pragma unroll
            for (int q = 0; q < 4; q++) acc[i][j][q] = 0.f;

    // load mapping: row = tid>>1 (0..127), colbase = (tid&1)*16
    int lr = tid >> 1, lc = (tid & 1) * 16;
    int arow = bm + lr; if (arow >= M) arow = M - 1;
    const __nv_bfloat16* wbh = g_wb + wboff;                        // Whi
    const __nv_bfloat16* wbl = g_wb + wboff + (size_t)N * K2;       // Wlo

    float4 fa[4];
    uint4  ub[2], vb[2];

    // prefetch chunk 0
    {
        const float* ap = g_agg + (size_t)arow * K + lc;
        fa[0] = *(const float4*)(ap);      fa[1] = *(const float4*)(ap + 4);
        fa[2] = *(const float4*)(ap + 8);  fa[3] = *(const float4*)(ap + 12);
        const __nv_bfloat16* bh = wbh + (size_t)(bn + lr) * K2 + lc;
        const __nv_bfloat16* bl = wbl + (size_t)(bn + lr) * K2 + lc;
        ub[0] = *(const uint4*)bh; ub[1] = *(const uint4*)(bh + 8);
        vb[0] = *(const uint4*)bl; vb[1] = *(const uint4*)(bl + 8);
    }

    #pragma unroll 1
    for (int c = 0; c < CHUNKS; c++) {
        // ---- STS current chunk ----
        #pragma unroll
        for (int q = 0; q < 4; q++) {
            uint32_t h01, l01, h23, l23;
            split2(fa[q].x, fa[q].y, h01, l01);
            split2(fa[q].z, fa[q].w, h23, l23);
            *(uint2*)&sAh[lr * 40 + lc + q * 4] = make_uint2(h01, h23);
            *(uint2*)&sAl[lr * 40 + lc + q * 4] = make_uint2(l01, l23);
        }
        *(uint2*)&sBh[lr * 40 + lc]      = make_uint2(ub[0].x, ub[0].y);
        *(uint2*)&sBh[lr * 40 + lc + 4]  = make_uint2(ub[0].z, ub[0].w);
        *(uint2*)&sBh[lr * 40 + lc + 8]  = make_uint2(ub[1].x, ub[1].y);
        *(uint2*)&sBh[lr * 40 + lc + 12] = make_uint2(ub[1].z, ub[1].w);
        *(uint2*)&sBl[lr * 40 + lc]      = make_uint2(vb[0].x, vb[0].y);
        *(uint2*)&sBl[lr * 40 + lc + 4]  = make_uint2(vb[0].z, vb[0].w);
        *(uint2*)&sBl[lr * 40 + lc + 8]  = make_uint2(vb[1].x, vb[1].y);
        *(uint2*)&sBl[lr * 40 + lc + 12] = make_uint2(vb[1].z, vb[1].w);
        __syncthreads();

        // ---- prefetch next chunk ----
        if (c + 1 < CHUNKS) {
            int kk = (c + 1) * 32;
            const float* Asrc = (kk < K) ? g_agg : Ax;
            int col0 = (kk < K) ? kk : (kk - K);
            const float* ap = Asrc + (size_t)arow * K + col0 + lc;
            fa[0] = *(const float4*)(ap);      fa[1] = *(const float4*)(ap + 4);
            fa[2] = *(const float4*)(ap + 8);  fa[3] = *(const float4*)(ap + 12);
            const __nv_bfloat16* bh = wbh + (size_t)(bn + lr) * K2 + kk + lc;
            const __nv_bfloat16* bl = wbl + (size_t)(bn + lr) * K2 + kk + lc;
            ub[0] = *(const uint4*)bh; ub[1] = *(const uint4*)(bh + 8);
            vb[0] = *(const uint4*)bl; vb[1] = *(const uint4*)(bl + 8);
        }

        // ---- MMA over 2 k16 steps ----
        #pragma unroll
        for (int ks = 0; ks < 2; ks++) {
            int lrow = lane & 15, lcolsel = (lane >> 4) * 8 + ks * 16;
            uint32_t ah[2][4], al[2][4];
            #pragma unroll
            for (int mi = 0; mi < 2; mi++) {
                ldmx4(ah[mi], smem_u32(&sAh[(wm + mi * 16 + lrow) * 40 + lcolsel]));
                ldmx4(al[mi], smem_u32(&sAl[(wm + mi * 16 + lrow) * 40 + lcolsel]));
            }
            #pragma unroll
            for (int nj = 0; nj < 4; nj++) {
                uint32_t bhf[4], blf[4];
                ldmx4(bhf, smem_u32(&sBh[(wn + nj * 16 + lrow) * 40 + lcolsel]));
                ldmx4(blf, smem_u32(&sBl[(wn + nj * 16 + lrow) * 40 + lcolsel]));
                #pragma unroll
                for (int mi = 0; mi < 2; mi++) {
                    float* a0 = acc[mi][nj * 2];
                    float* a1 = acc[mi][nj * 2 + 1];
                    mma16816(a0, ah[mi], bhf[0], bhf[2]);
                    mma16816(a0, ah[mi], blf[0], blf[2]);
                    mma16816(a0, al[mi], bhf[0], bhf[2]);
                    mma16816(a1, ah[mi], bhf[1], bhf[3]);
                    mma16816(a1, ah[mi], blf[1], blf[3]);
                    mma16816(a1, al[mi], bhf[1], bhf[3]);
                }
            }
        }
        __syncthreads();
    }

    // ---- epilogue ----
    int tg = lane & 3, g = lane >> 2;
    #pragma unroll
    for (int mi = 0; mi < 2; mi++) {
        int r0 = bm + wm + mi * 16 + g;
        int r1 = r0 + 8;
        #pragma unroll
        for (int ni = 0; ni < 8; ni++) {
            int col = bn + wn + ni * 8 + tg * 2;
            float b0 = __ldg(&bias[col]), b1 = __ldg(&bias[col + 1]);
            float v0 = acc[mi][ni][0] + b0, v1 = acc[mi][ni][1] + b1;
            float v2 = acc[mi][ni][2] + b0, v3 = acc[mi][ni][3] + b1;
            if (RELU) {
                v0 = fmaxf(v0, 0.f); v1 = fmaxf(v1, 0.f);
                v2 = fmaxf(v2, 0.f); v3 = fmaxf(v3, 0.f);
            }
            if (r0 < M) *(float2*)(out + (size_t)r0 * N + col) = make_float2(v0, v1);
            if (r1 < M) *(float2*)(out + (size_t)r1 * N + col) = make_float2(v2, v3);
        }
    }
}

// ---------------- launch ----------------
extern "C" void kernel_launch(void* const* d_in, const int* in_sizes, int n_in,
                              void* d_out, int out_size) {
    const float* x   = (const float*)d_in[0];
    const int*   ei  = (const int*)d_in[1];     // int32 edge_index [2, E]
    const float* Wl0 = (const float*)d_in[2];
    const float* b0  = (const float*)d_in[3];
    const float* Wr0 = (const float*)d_in[4];
    const float* Wl1 = (const float*)d_in[5];
    const float* b1  = (const float*)d_in[6];
    const float* Wr1 = (const float*)d_in[7];
    const float* Wl2 = (const float*)d_in[8];
    const float* b2  = (const float*)d_in[9];
    const float* Wr2 = (const float*)d_in[10];
    float* out = (float*)d_out;

    const int E = in_sizes[1] / 2;
    const int M = in_sizes[0] / 128;
    const int* src = ei;
    const int* dst = ei + E;

    // --- CSR build ---
    zero_deg_kernel<<<(M + 255) / 256, 256>>>(M);
    hist_kernel<<<2048, 256>>>(dst, E, M);
    scan_kernel<<<1, 1024>>>(M);
    fill_kernel<<<2048, 256>>>(src, dst, E, M);
    invdeg_kernel<<<(M + 255) / 256, 256>>>(M);

    // --- weight split prep ---
    prep_w<<<256, 256>>>(Wl0, Wr0, 128, 256, 0);        // 256x256 -> off 0
    prep_w<<<512, 256>>>(Wl1, Wr1, 256, 256, 131072);   // 256x512 -> off 131072
    prep_w<<<256, 256>>>(Wl2, Wr2, 256, 128, 393216);   // 128x512 -> off 393216

    const int agg_blocks = (M * 32 + 255) / 256;
    dim3 g2((M + 127) / 128, 2), g1((M + 127) / 128, 1);

    // --- layer 0: 128 -> 256, relu ---
    aggregate_kernel<128><<<agg_blocks, 256>>>(x, 0, M);
    gemm_mma<256, 256, true><<<g2, 256>>>(x, 0, b0, nullptr, 1, 0, M);

    // --- layer 1: 256 -> 256, relu ---
    aggregate_kernel<256><<<agg_blocks, 256>>>(nullptr, 1, M);
    gemm_mma<512, 256, true><<<g2, 256>>>(nullptr, 1, b1, nullptr, 2, 131072, M);

    // --- layer 2: 256 -> 128, no act ---
    aggregate_kernel<256><<<agg_blocks, 256>>>(nullptr, 2, M);
    gemm_mma<512, 128, false><<<g1, 256>>>(nullptr, 2, b2, out, 0, 393216, M);
}

// round 7
// speedup vs baseline: 2.0887x; 1.1935x over previous
#include <cuda_runtime.h>
#include <cuda_bf16.h>
#include <cuda_fp16.h>
#include <cstdint>

#define NN 100000
#define NE 1600000

// ---------------- device scratch (allocation-free; ONLY touched from device code) ----------------
__device__ int   g_degi[NN];
__device__ int   g_rowptr[NN + 1];
__device__ int   g_cursor[NN];
__device__ int   g_adj[NE];
__device__ __align__(16) float g_invdeg[NN];
__device__ __align__(16) float g_agg[(size_t)NN * 256];
__device__ __align__(16) float g_h1[(size_t)NN * 256];
__device__ __align__(16) float g_h2[(size_t)NN * 256];
// fp16 weights, per layer: W[N][2K] rows k-contiguous.
// L0 @0 (256*256=65536), L1 @65536 (256*512=131072), L2 @196608 (128*512=65536)
__device__ __align__(16) __half g_wf[262144];

// Buffer selectors: 0 = external pointer (kernel arg), 1 = g_h1, 2 = g_h2
__device__ __forceinline__ const float* sel_cbuf(int sel, const float* ext) {
    if (sel == 1) return g_h1;
    if (sel == 2) return g_h2;
    return ext;
}
__device__ __forceinline__ float* sel_buf(int sel, float* ext) {
    if (sel == 1) return g_h1;
    if (sel == 2) return g_h2;
    return ext;
}

// ---------------- helpers ----------------
__device__ __forceinline__ float4 f4add(float4 a, float4 b) {
    a.x += b.x; a.y += b.y; a.z += b.z; a.w += b.w; return a;
}
__device__ __forceinline__ float4 f4scale(float4 a, float s) {
    a.x *= s; a.y *= s; a.z *= s; a.w *= s; return a;
}
// fp16 hi/lo split of two floats, packed as half2 raw bits
__device__ __forceinline__ void splith2(float a, float b, uint32_t& hi, uint32_t& lo) {
    __half ha = __float2half(a), hb = __float2half(b);
    float la = a - __half2float(ha), lb = b - __half2float(hb);
    __half2 th; th.x = ha; th.y = hb;
    __half2 tl; tl.x = __float2half(la); tl.y = __float2half(lb);
    hi = *reinterpret_cast<uint32_t*>(&th);
    lo = *reinterpret_cast<uint32_t*>(&tl);
}
__device__ __forceinline__ uint32_t smem_u32(const void* p) {
    uint32_t r;
    asm("{ .reg .u64 t; cvta.to.shared.u64 t, %1; cvt.u32.u64 %0, t; }" : "=r"(r) : "l"(p));
    return r;
}
__device__ __forceinline__ void ldmx4(uint32_t* r, uint32_t addr) {
    asm volatile("ldmatrix.sync.aligned.m8n8.x4.shared.b16 {%0,%1,%2,%3}, [%4];"
                 : "=r"(r[0]), "=r"(r[1]), "=r"(r[2]), "=r"(r[3]) : "r"(addr));
}
__device__ __forceinline__ void mma16816(float* c, const uint32_t* a, uint32_t b0, uint32_t b1) {
    asm volatile("mma.sync.aligned.m16n8k16.row.col.f32.f16.f16.f32 "
                 "{%0,%1,%2,%3}, {%4,%5,%6,%7}, {%8,%9}, {%0,%1,%2,%3};"
                 : "+f"(c[0]), "+f"(c[1]), "+f"(c[2]), "+f"(c[3])
                 : "r"(a[0]), "r"(a[1]), "r"(a[2]), "r"(a[3]), "r"(b0), "r"(b1));
}

// ---------------- CSR build ----------------
__global__ void zero_deg_kernel(int n) {
    int i = blockIdx.x * blockDim.x + threadIdx.x;
    if (i < n) g_degi[i] = 0;
}
__global__ void hist_kernel(const int* __restrict__ dst, int E, int n) {
    int i = blockIdx.x * blockDim.x + threadIdx.x;
    int stride = gridDim.x * blockDim.x;
    for (; i < E; i += stride) {
        int d = dst[i];
        if ((unsigned)d < (unsigned)n) atomicAdd(&g_degi[d], 1);
    }
}
__global__ void scan_kernel(int n) {
    __shared__ int warp_sums[32];
    __shared__ int s_carry;
    int tid = threadIdx.x, lane = tid & 31, wid = tid >> 5;
    if (tid == 0) s_carry = 0;
    __syncthreads();
    for (int base = 0; base < n; base += 1024) {
        int i = base + tid;
        int v = (i < n) ? g_degi[i] : 0;
        int s = v;
        #pragma unroll
        for (int off = 1; off < 32; off <<= 1) {
            int t = __shfl_up_sync(0xffffffffu, s, off);
            if (lane >= off) s += t;
        }
        if (lane == 31) warp_sums[wid] = s;
        __syncthreads();
        if (wid == 0) {
            int t2 = warp_sums[lane];
            #pragma unroll
            for (int off = 1; off < 32; off <<= 1) {
                int t = __shfl_up_sync(0xffffffffu, t2, off);
                if (lane >= off) t2 += t;
            }
            warp_sums[lane] = t2;
        }
        __syncthreads();
        int warp_off = (wid > 0) ? warp_sums[wid - 1] : 0;
        int incl = s + warp_off;
        int carry = s_carry;
        int excl = carry + incl - v;
        if (i < n) { g_rowptr[i] = excl; g_cursor[i] = excl; }
        __syncthreads();
        if (tid == 1023) s_carry = carry + warp_sums[31];
        __syncthreads();
    }
    if (threadIdx.x == 0) g_rowptr[n] = s_carry;
}
__global__ void fill_kernel(const int* __restrict__ src, const int* __restrict__ dst, int E, int n) {
    int i = blockIdx.x * blockDim.x + threadIdx.x;
    int stride = gridDim.x * blockDim.x;
    for (; i < E; i += stride) {
        int d = dst[i], s = src[i];
        if ((unsigned)d < (unsigned)n && (unsigned)s < (unsigned)n) {
            int slot = atomicAdd(&g_cursor[d], 1);
            if ((unsigned)slot < (unsigned)NE) g_adj[slot] = s;
        }
    }
}
__global__ void invdeg_kernel(int n) {
    int i = blockIdx.x * blockDim.x + threadIdx.x;
    if (i < n) g_invdeg[i] = 1.0f / fmaxf((float)g_degi[i], 1.0f);
}

// ---------------- weight prep: fp16 W[N][2K], k-contiguous rows ----------------
__global__ void prep_w(const float* __restrict__ Wl, const float* __restrict__ Wr,
                       int K, int N, int off) {
    int K2 = 2 * K;
    int total = N * K2;
    for (int i = blockIdx.x * blockDim.x + threadIdx.x; i < total; i += gridDim.x * blockDim.x) {
        int n = i / K2, k = i % K2;
        float w = (k < K) ? Wl[(size_t)k * N + n] : Wr[(size_t)(k - K) * N + n];
        g_wf[(size_t)off + (size_t)n * K2 + k] = __float2half(w);
    }
}

// ---------------- mean aggregation (CSR gather, warp per node) — proven in R4 ----------------
template <int D>
__global__ void __launch_bounds__(256) aggregate_kernel(
    const float* __restrict__ ext, int src_sel, int n) {
    const float* feat = sel_cbuf(src_sel, ext);
    int w = (blockIdx.x * blockDim.x + threadIdx.x) >> 5;
    int lane = threadIdx.x & 31;
    if (w >= n) return;
    int start = g_rowptr[w];
    int end   = g_rowptr[w + 1];
    constexpr int C = D / 128;
    float4 acc[C];
    #pragma unroll
    for (int c = 0; c < C; c++) acc[c] = make_float4(0.f, 0.f, 0.f, 0.f);
    for (int j = start; j < end; j++) {
        int s = g_adj[j];
        if ((unsigned)s >= (unsigned)n) continue;
        const float4* xs = (const float4*)(feat + (size_t)s * D);
        #pragma unroll
        for (int c = 0; c < C; c++) acc[c] = f4add(acc[c], xs[lane + 32 * c]);
    }
    float sc = g_invdeg[w];
    float4* o = (float4*)(g_agg + (size_t)w * D);
    #pragma unroll
    for (int c = 0; c < C; c++) o[lane + 32 * c] = f4scale(acc[c], sc);
}

// ---------------- tensor-core dual GEMM, fp16 A-split 2-pass ----------------
// out[M,N] = act( [g_agg | X] @ W + b ), computed as Ahi@W + Alo@W (A exact to ~2^-22, W fp16).
// BM=128, BN=128, BK=32; 8 warps of 32x64; m16n8k16 fp16 MMA via ldmatrix.
template <int K2, int N, bool RELU>
__global__ void __launch_bounds__(256) gemm_mma(
    const float* __restrict__ x_ext, int x_sel,
    const float* __restrict__ bias,
    float* __restrict__ out_ext, int out_sel,
    int wboff, int M) {
    // padded smem: row stride 40 halves (80B) -> conflict-free ldmatrix
    __shared__ __half sAh[128 * 40];
    __shared__ __half sAl[128 * 40];
    __shared__ __half sB[128 * 40];

    const float* Ax = sel_cbuf(x_sel, x_ext);
    float* out = sel_buf(out_sel, out_ext);
    constexpr int K = K2 / 2;
    constexpr int CHUNKS = K2 / 32;

    int tid = threadIdx.x;
    int wid = tid >> 5, lane = tid & 31;
    int bm = blockIdx.x * 128, bn = blockIdx.y * 128;
    int wm = (wid & 3) * 32;     // warp m offset
    int wn = (wid >> 2) * 64;    // warp n offset

    float acc[2][8][4];
    #pragma unroll
    for (int i = 0; i < 2; i++)
        #pragma unroll
        for (int j = 0; j < 8; j++)
            #pragma unroll
            for (int q = 0; q < 4; q++) acc[i][j][q] = 0.f;

    // load mapping: row = tid>>1 (0..127), colbase = (tid&1)*16
    int lr = tid >> 1, lc = (tid & 1) * 16;
    int arow = bm + lr; if (arow >= M) arow = M - 1;
    const __half* wb = g_wf + wboff;

    float4 fa[4];
    uint4  ub[2];

    // prefetch chunk 0
    {
        const float* ap = g_agg + (size_t)arow * K + lc;
        fa[0] = *(const float4*)(ap);      fa[1] = *(const float4*)(ap + 4);
        fa[2] = *(const float4*)(ap + 8);  fa[3] = *(const float4*)(ap + 12);
        const __half* bh = wb + (size_t)(bn + lr) * K2 + lc;
        ub[0] = *(const uint4*)bh; ub[1] = *(const uint4*)(bh + 8);
    }

    #pragma unroll 1
    for (int c = 0; c < CHUNKS; c++) {
        // ---- STS current chunk ----
        #pragma unroll
        for (int q = 0; q < 4; q++) {
            uint32_t h01, l01, h23, l23;
            splith2(fa[q].x, fa[q].y, h01, l01);
            splith2(fa[q].z, fa[q].w, h23, l23);
            *(uint2*)&sAh[lr * 40 + lc + q * 4] = make_uint2(h01, h23);
            *(uint2*)&sAl[lr * 40 + lc + q * 4] = make_uint2(l01, l23);
        }
        *(uint2*)&sB[lr * 40 + lc]      = make_uint2(ub[0].x, ub[0].y);
        *(uint2*)&sB[lr * 40 + lc + 4]  = make_uint2(ub[0].z, ub[0].w);
        *(uint2*)&sB[lr * 40 + lc + 8]  = make_uint2(ub[1].x, ub[1].y);
        *(uint2*)&sB[lr * 40 + lc + 12] = make_uint2(ub[1].z, ub[1].w);
        __syncthreads();

        // ---- prefetch next chunk ----
        if (c + 1 < CHUNKS) {
            int kk = (c + 1) * 32;
            const float* Asrc = (kk < K) ? g_agg : Ax;
            int col0 = (kk < K) ? kk : (kk - K);
            const float* ap = Asrc + (size_t)arow * K + col0 + lc;
            fa[0] = *(const float4*)(ap);      fa[1] = *(const float4*)(ap + 4);
            fa[2] = *(const float4*)(ap + 8);  fa[3] = *(const float4*)(ap + 12);
            const __half* bh = wb + (size_t)(bn + lr) * K2 + kk + lc;
            ub[0] = *(const uint4*)bh; ub[1] = *(const uint4*)(bh + 8);
        }

        // ---- MMA over 2 k16 steps ----
        #pragma unroll
        for (int ks = 0; ks < 2; ks++) {
            int lrow = lane & 15, lcolsel = (lane >> 4) * 8 + ks * 16;
            uint32_t ah[2][4], al[2][4];
            #pragma unroll
            for (int mi = 0; mi < 2; mi++) {
                ldmx4(ah[mi], smem_u32(&sAh[(wm + mi * 16 + lrow) * 40 + lcolsel]));
                ldmx4(al[mi], smem_u32(&sAl[(wm + mi * 16 + lrow) * 40 + lcolsel]));
            }
            #pragma unroll
            for (int nj = 0; nj < 4; nj++) {
                uint32_t bf[4];
                ldmx4(bf, smem_u32(&sB[(wn + nj * 16 + lrow) * 40 + lcolsel]));
                #pragma unroll
                for (int mi = 0; mi < 2; mi++) {
                    float* a0 = acc[mi][nj * 2];
                    float* a1 = acc[mi][nj * 2 + 1];
                    mma16816(a0, ah[mi], bf[0], bf[2]);
                    mma16816(a0, al[mi], bf[0], bf[2]);
                    mma16816(a1, ah[mi], bf[1], bf[3]);
                    mma16816(a1, al[mi], bf[1], bf[3]);
                }
            }
        }
        __syncthreads();
    }

    // ---- epilogue ----
    int tg = lane & 3, g = lane >> 2;
    #pragma unroll
    for (int mi = 0; mi < 2; mi++) {
        int r0 = bm + wm + mi * 16 + g;
        int r1 = r0 + 8;
        #pragma unroll
        for (int ni = 0; ni < 8; ni++) {
            int col = bn + wn + ni * 8 + tg * 2;
            float b0 = __ldg(&bias[col]), b1 = __ldg(&bias[col + 1]);
            float v0 = acc[mi][ni][0] + b0, v1 = acc[mi][ni][1] + b1;
            float v2 = acc[mi][ni][2] + b0, v3 = acc[mi][ni][3] + b1;
            if (RELU) {
                v0 = fmaxf(v0, 0.f); v1 = fmaxf(v1, 0.f);
                v2 = fmaxf(v2, 0.f); v3 = fmaxf(v3, 0.f);
            }
            if (r0 < M) *(float2*)(out + (size_t)r0 * N + col) = make_float2(v0, v1);
            if (r1 < M) *(float2*)(out + (size_t)r1 * N + col) = make_float2(v2, v3);
        }
    }
}

// ---------------- launch ----------------
extern "C" void kernel_launch(void* const* d_in, const int* in_sizes, int n_in,
                              void* d_out, int out_size) {
    const float* x   = (const float*)d_in[0];
    const int*   ei  = (const int*)d_in[1];     // int32 edge_index [2, E]
    const float* Wl0 = (const float*)d_in[2];
    const float* b0  = (const float*)d_in[3];
    const float* Wr0 = (const float*)d_in[4];
    const float* Wl1 = (const float*)d_in[5];
    const float* b1  = (const float*)d_in[6];
    const float* Wr1 = (const float*)d_in[7];
    const float* Wl2 = (const float*)d_in[8];
    const float* b2  = (const float*)d_in[9];
    const float* Wr2 = (const float*)d_in[10];
    float* out = (float*)d_out;

    const int E = in_sizes[1] / 2;
    const int M = in_sizes[0] / 128;
    const int* src = ei;
    const int* dst = ei + E;

    // --- CSR build ---
    zero_deg_kernel<<<(M + 255) / 256, 256>>>(M);
    hist_kernel<<<2048, 256>>>(dst, E, M);
    scan_kernel<<<1, 1024>>>(M);
    fill_kernel<<<2048, 256>>>(src, dst, E, M);
    invdeg_kernel<<<(M + 255) / 256, 256>>>(M);

    // --- weight prep (fp16) ---
    prep_w<<<256, 256>>>(Wl0, Wr0, 128, 256, 0);        // 256x256 -> off 0
    prep_w<<<512, 256>>>(Wl1, Wr1, 256, 256, 65536);    // 256x512 -> off 65536
    prep_w<<<256, 256>>>(Wl2, Wr2, 256, 128, 196608);   // 128x512 -> off 196608

    const int agg_blocks = (M * 32 + 255) / 256;
    dim3 g2((M + 127) / 128, 2), g1((M + 127) / 128, 1);

    // --- layer 0: 128 -> 256, relu ---
    aggregate_kernel<128><<<agg_blocks, 256>>>(x, 0, M);
    gemm_mma<256, 256, true><<<g2, 256>>>(x, 0, b0, nullptr, 1, 0, M);

    // --- layer 1: 256 -> 256, relu ---
    aggregate_kernel<256><<<agg_blocks, 256>>>(nullptr, 1, M);
    gemm_mma<512, 256, true><<<g2, 256>>>(nullptr, 1, b1, nullptr, 2, 65536, M);

    // --- layer 2: 256 -> 128, no act ---
    aggregate_kernel<256><<<agg_blocks, 256>>>(nullptr, 2, M);
    gemm_mma<512, 128, false><<<g1, 256>>>(nullptr, 2, b2, out, 0, 196608, M);
}

// round 8
// speedup vs baseline: 3.1844x; 1.5246x over previous
#include <cuda_runtime.h>
#include <cuda_fp16.h>
#include <cstdint>

#define NN 100000
#define NE 1600000

// ---------------- device scratch (allocation-free; ONLY touched from device code) ----------------
__device__ int   g_degi[NN];
__device__ int   g_rowptr[NN + 1];
__device__ int   g_cursor[NN];
__device__ int   g_adj[NE];
__device__ __align__(16) float  g_invdeg[NN];
// fp16 activations
__device__ __align__(16) __half g_x16[(size_t)NN * 128];
__device__ __align__(16) __half g_h116[(size_t)NN * 256];
__device__ __align__(16) __half g_h216[(size_t)NN * 256];
__device__ __align__(16) __half g_agg16[(size_t)NN * 256];
// fp16 weights, per layer: W[N][2K] rows k-contiguous.
// L0 @0 (65536), L1 @65536 (131072), L2 @196608 (65536)
__device__ __align__(16) __half g_wf[262144];

// fp16 plane selectors: 0 = g_x16, 1 = g_h116, 2 = g_h216
__device__ __forceinline__ const __half* sel_h(int sel) {
    if (sel == 1) return g_h116;
    if (sel == 2) return g_h216;
    return g_x16;
}

// ---------------- helpers ----------------
__device__ __forceinline__ void hacc(uint32_t u, float& a, float& b) {
    __half2 t = *reinterpret_cast<__half2*>(&u);
    float2 f = __half22float2(t);
    a += f.x; b += f.y;
}
__device__ __forceinline__ uint32_t packh2(float a, float b) {
    __half2 t = __floats2half2_rn(a, b);
    return *reinterpret_cast<uint32_t*>(&t);
}
__device__ __forceinline__ uint32_t smem_u32(const void* p) {
    uint32_t r;
    asm("{ .reg .u64 t; cvta.to.shared.u64 t, %1; cvt.u32.u64 %0, t; }" : "=r"(r) : "l"(p));
    return r;
}
__device__ __forceinline__ void ldmx4(uint32_t* r, uint32_t addr) {
    asm volatile("ldmatrix.sync.aligned.m8n8.x4.shared.b16 {%0,%1,%2,%3}, [%4];"
                 : "=r"(r[0]), "=r"(r[1]), "=r"(r[2]), "=r"(r[3]) : "r"(addr));
}
__device__ __forceinline__ void mma16816(float* c, const uint32_t* a, uint32_t b0, uint32_t b1) {
    asm volatile("mma.sync.aligned.m16n8k16.row.col.f32.f16.f16.f32 "
                 "{%0,%1,%2,%3}, {%4,%5,%6,%7}, {%8,%9}, {%0,%1,%2,%3};"
                 : "+f"(c[0]), "+f"(c[1]), "+f"(c[2]), "+f"(c[3])
                 : "r"(a[0]), "r"(a[1]), "r"(a[2]), "r"(a[3]), "r"(b0), "r"(b1));
}

// ---------------- CSR build ----------------
__global__ void zero_deg_kernel(int n) {
    int i = blockIdx.x * blockDim.x + threadIdx.x;
    if (i < n) g_degi[i] = 0;
}
__global__ void hist_kernel(const int* __restrict__ dst, int E, int n) {
    int i = blockIdx.x * blockDim.x + threadIdx.x;
    int stride = gridDim.x * blockDim.x;
    for (; i < E; i += stride) {
        int d = dst[i];
        if ((unsigned)d < (unsigned)n) atomicAdd(&g_degi[d], 1);
    }
}
__global__ void scan_kernel(int n) {
    __shared__ int warp_sums[32];
    __shared__ int s_carry;
    int tid = threadIdx.x, lane = tid & 31, wid = tid >> 5;
    if (tid == 0) s_carry = 0;
    __syncthreads();
    for (int base = 0; base < n; base += 1024) {
        int i = base + tid;
        int v = (i < n) ? g_degi[i] : 0;
        int s = v;
        #pragma unroll
        for (int off = 1; off < 32; off <<= 1) {
            int t = __shfl_up_sync(0xffffffffu, s, off);
            if (lane >= off) s += t;
        }
        if (lane == 31) warp_sums[wid] = s;
        __syncthreads();
        if (wid == 0) {
            int t2 = warp_sums[lane];
            #pragma unroll
            for (int off = 1; off < 32; off <<= 1) {
                int t = __shfl_up_sync(0xffffffffu, t2, off);
                if (lane >= off) t2 += t;
            }
            warp_sums[lane] = t2;
        }
        __syncthreads();
        int warp_off = (wid > 0) ? warp_sums[wid - 1] : 0;
        int incl = s + warp_off;
        int carry = s_carry;
        int excl = carry + incl - v;
        if (i < n) { g_rowptr[i] = excl; g_cursor[i] = excl; }
        __syncthreads();
        if (tid == 1023) s_carry = carry + warp_sums[31];
        __syncthreads();
    }
    if (threadIdx.x == 0) g_rowptr[n] = s_carry;
}
__global__ void fill_kernel(const int* __restrict__ src, const int* __restrict__ dst, int E, int n) {
    int i = blockIdx.x * blockDim.x + threadIdx.x;
    int stride = gridDim.x * blockDim.x;
    for (; i < E; i += stride) {
        int d = dst[i], s = src[i];
        if ((unsigned)d < (unsigned)n && (unsigned)s < (unsigned)n) {
            int slot = atomicAdd(&g_cursor[d], 1);
            if ((unsigned)slot < (unsigned)NE) g_adj[slot] = s;
        }
    }
}
__global__ void invdeg_kernel(int n) {
    int i = blockIdx.x * blockDim.x + threadIdx.x;
    if (i < n) g_invdeg[i] = 1.0f / fmaxf((float)g_degi[i], 1.0f);
}

// ---------------- prep: fp16 W[N][2K]; x -> fp16 ----------------
__global__ void prep_w(const float* __restrict__ Wl, const float* __restrict__ Wr,
                       int K, int N, int off) {
    int K2 = 2 * K;
    int total = N * K2;
    for (int i = blockIdx.x * blockDim.x + threadIdx.x; i < total; i += gridDim.x * blockDim.x) {
        int n = i / K2, k = i % K2;
        float w = (k < K) ? Wl[(size_t)k * N + n] : Wr[(size_t)(k - K) * N + n];
        g_wf[(size_t)off + (size_t)n * K2 + k] = __float2half(w);
    }
}
__global__ void conv_x(const float* __restrict__ x, int total4) {
    for (int i = blockIdx.x * blockDim.x + threadIdx.x; i < total4; i += gridDim.x * blockDim.x) {
        float4 v = *(const float4*)(x + (size_t)i * 4);
        *(uint2*)(g_x16 + (size_t)i * 4) = make_uint2(packh2(v.x, v.y), packh2(v.z, v.w));
    }
}

// ---------------- mean aggregation: fp16 gather, fp32 accumulate, fp16 write ----------------
template <int D>
__global__ void __launch_bounds__(256) aggregate_kernel(int src_sel, int n) {
    const __half* feat = sel_h(src_sel);
    int w = (blockIdx.x * blockDim.x + threadIdx.x) >> 5;
    int lane = threadIdx.x & 31;
    if (w >= n) return;
    int j = g_rowptr[w], end = g_rowptr[w + 1];

    if (D == 256) {
        float acc[8] = {0.f, 0.f, 0.f, 0.f, 0.f, 0.f, 0.f, 0.f};
        for (; j + 1 < end; j += 2) {
            int s0 = g_adj[j], s1 = g_adj[j + 1];
            uint4 va = *(const uint4*)(feat + (size_t)s0 * 256 + lane * 8);
            uint4 vb = *(const uint4*)(feat + (size_t)s1 * 256 + lane * 8);
            hacc(va.x, acc[0], acc[1]); hacc(va.y, acc[2], acc[3]);
            hacc(va.z, acc[4], acc[5]); hacc(va.w, acc[6], acc[7]);
            hacc(vb.x, acc[0], acc[1]); hacc(vb.y, acc[2], acc[3]);
            hacc(vb.z, acc[4], acc[5]); hacc(vb.w, acc[6], acc[7]);
        }
        if (j < end) {
            int s0 = g_adj[j];
            uint4 va = *(const uint4*)(feat + (size_t)s0 * 256 + lane * 8);
            hacc(va.x, acc[0], acc[1]); hacc(va.y, acc[2], acc[3]);
            hacc(va.z, acc[4], acc[5]); hacc(va.w, acc[6], acc[7]);
        }
        float sc = g_invdeg[w];
        uint4 o;
        o.x = packh2(acc[0] * sc, acc[1] * sc);
        o.y = packh2(acc[2] * sc, acc[3] * sc);
        o.z = packh2(acc[4] * sc, acc[5] * sc);
        o.w = packh2(acc[6] * sc, acc[7] * sc);
        *(uint4*)(g_agg16 + (size_t)w * 256 + lane * 8) = o;
    } else {
        float acc[4] = {0.f, 0.f, 0.f, 0.f};
        for (; j + 1 < end; j += 2) {
            int s0 = g_adj[j], s1 = g_adj[j + 1];
            uint2 va = *(const uint2*)(feat + (size_t)s0 * 128 + lane * 4);
            uint2 vb = *(const uint2*)(feat + (size_t)s1 * 128 + lane * 4);
            hacc(va.x, acc[0], acc[1]); hacc(va.y, acc[2], acc[3]);
            hacc(vb.x, acc[0], acc[1]); hacc(vb.y, acc[2], acc[3]);
        }
        if (j < end) {
            int s0 = g_adj[j];
            uint2 va = *(const uint2*)(feat + (size_t)s0 * 128 + lane * 4);
            hacc(va.x, acc[0], acc[1]); hacc(va.y, acc[2], acc[3]);
        }
        float sc = g_invdeg[w];
        *(uint2*)(g_agg16 + (size_t)w * 128 + lane * 4) =
            make_uint2(packh2(acc[0] * sc, acc[1] * sc), packh2(acc[2] * sc, acc[3] * sc));
    }
}

// ---------------- tensor-core dual GEMM, pure fp16 single pass ----------------
// out[M,N] = act( [agg16 | in16] @ W + b ).  BM=128, BN=128, BK=32; 8 warps of 32x64.
template <int K2, int N, bool RELU, bool OUT16>
__global__ void __launch_bounds__(256) gemm_mma(
    int x_sel, const float* __restrict__ bias,
    float* __restrict__ out_ext, int out_sel, int wboff, int M) {
    __shared__ __half sA[128 * 40];
    __shared__ __half sB[128 * 40];

    const __half* Ax = sel_h(x_sel);
    constexpr int K = K2 / 2;
    constexpr int CHUNKS = K2 / 32;

    int tid = threadIdx.x;
    int wid = tid >> 5, lane = tid & 31;
    int bm = blockIdx.x * 128, bn = blockIdx.y * 128;
    int wm = (wid & 3) * 32;
    int wn = (wid >> 2) * 64;

    float acc[2][8][4];
    #pragma unroll
    for (int i = 0; i < 2; i++)
        #pragma unroll
        for (int j = 0; j < 8; j++)
            #pragma unroll
            for (int q = 0; q < 4; q++) acc[i][j][q] = 0.f;

    int lr = tid >> 1, lc = (tid & 1) * 16;
    int arow = bm + lr; if (arow >= M) arow = M - 1;
    const __half* wb = g_wf + wboff;

    uint4 ua[2], ub[2];
    {   // prefetch chunk 0 (always from agg16)
        const __half* ap = g_agg16 + (size_t)arow * K + lc;
        ua[0] = *(const uint4*)ap; ua[1] = *(const uint4*)(ap + 8);
        const __half* bp = wb + (size_t)(bn + lr) * K2 + lc;
        ub[0] = *(const uint4*)bp; ub[1] = *(const uint4*)(bp + 8);
    }

    #pragma unroll 1
    for (int c = 0; c < CHUNKS; c++) {
        *(uint4*)&sA[lr * 40 + lc]     = ua[0];
        *(uint4*)&sA[lr * 40 + lc + 8] = ua[1];
        *(uint4*)&sB[lr * 40 + lc]     = ub[0];
        *(uint4*)&sB[lr * 40 + lc + 8] = ub[1];
        __syncthreads();

        if (c + 1 < CHUNKS) {
            int kk = (c + 1) * 32;
            const __half* Asrc = (kk < K) ? g_agg16 : Ax;
            int col0 = (kk < K) ? kk : (kk - K);
            const __half* ap = Asrc + (size_t)arow * K + col0 + lc;
            ua[0] = *(const uint4*)ap; ua[1] = *(const uint4*)(ap + 8);
            const __half* bp = wb + (size_t)(bn + lr) * K2 + kk + lc;
            ub[0] = *(const uint4*)bp; ub[1] = *(const uint4*)(bp + 8);
        }

        #pragma unroll
        for (int ks = 0; ks < 2; ks++) {
            int lrow = lane & 15, lcolsel = (lane >> 4) * 8 + ks * 16;
            uint32_t a[2][4];
            #pragma unroll
            for (int mi = 0; mi < 2; mi++)
                ldmx4(a[mi], smem_u32(&sA[(wm + mi * 16 + lrow) * 40 + lcolsel]));
            #pragma unroll
            for (int nj = 0; nj < 4; nj++) {
                uint32_t bf[4];
                ldmx4(bf, smem_u32(&sB[(wn + nj * 16 + lrow) * 40 + lcolsel]));
                #pragma unroll
                for (int mi = 0; mi < 2; mi++) {
                    mma16816(acc[mi][nj * 2],     a[mi], bf[0], bf[2]);
                    mma16816(acc[mi][nj * 2 + 1], a[mi], bf[1], bf[3]);
                }
            }
        }
        __syncthreads();
    }

    // ---- epilogue ----
    int tg = lane & 3, g = lane >> 2;
    __half* out16 = (out_sel == 1) ? g_h116 : g_h216;
    #pragma unroll
    for (int mi = 0; mi < 2; mi++) {
        int r0 = bm + wm + mi * 16 + g;
        int r1 = r0 + 8;
        #pragma unroll
        for (int ni = 0; ni < 8; ni++) {
            int col = bn + wn + ni * 8 + tg * 2;
            float b0 = __ldg(&bias[col]), b1 = __ldg(&bias[col + 1]);
            float v0 = acc[mi][ni][0] + b0, v1 = acc[mi][ni][1] + b1;
            float v2 = acc[mi][ni][2] + b0, v3 = acc[mi][ni][3] + b1;
            if (RELU) {
                v0 = fmaxf(v0, 0.f); v1 = fmaxf(v1, 0.f);
                v2 = fmaxf(v2, 0.f); v3 = fmaxf(v3, 0.f);
            }
            if (OUT16) {
                if (r0 < M) *(uint32_t*)(out16 + (size_t)r0 * N + col) = packh2(v0, v1);
                if (r1 < M) *(uint32_t*)(out16 + (size_t)r1 * N + col) = packh2(v2, v3);
            } else {
                if (r0 < M) *(float2*)(out_ext + (size_t)r0 * N + col) = make_float2(v0, v1);
                if (r1 < M) *(float2*)(out_ext + (size_t)r1 * N + col) = make_float2(v2, v3);
            }
        }
    }
}

// ---------------- launch ----------------
extern "C" void kernel_launch(void* const* d_in, const int* in_sizes, int n_in,
                              void* d_out, int out_size) {
    const float* x   = (const float*)d_in[0];
    const int*   ei  = (const int*)d_in[1];     // int32 edge_index [2, E]
    const float* Wl0 = (const float*)d_in[2];
    const float* b0  = (const float*)d_in[3];
    const float* Wr0 = (const float*)d_in[4];
    const float* Wl1 = (const float*)d_in[5];
    const float* b1  = (const float*)d_in[6];
    const float* Wr1 = (const float*)d_in[7];
    const float* Wl2 = (const float*)d_in[8];
    const float* b2  = (const float*)d_in[9];
    const float* Wr2 = (const float*)d_in[10];
    float* out = (float*)d_out;

    const int E = in_sizes[1] / 2;
    const int M = in_sizes[0] / 128;
    const int* src = ei;
    const int* dst = ei + E;

    // --- CSR build ---
    zero_deg_kernel<<<(M + 255) / 256, 256>>>(M);
    hist_kernel<<<2048, 256>>>(dst, E, M);
    scan_kernel<<<1, 1024>>>(M);
    fill_kernel<<<2048, 256>>>(src, dst, E, M);
    invdeg_kernel<<<(M + 255) / 256, 256>>>(M);

    // --- prep: fp16 weights + fp16 x ---
    prep_w<<<256, 256>>>(Wl0, Wr0, 128, 256, 0);
    prep_w<<<512, 256>>>(Wl1, Wr1, 256, 256, 65536);
    prep_w<<<256, 256>>>(Wl2, Wr2, 256, 128, 196608);
    conv_x<<<2048, 256>>>(x, M * 32);

    const int agg_blocks = (M * 32 + 255) / 256;
    dim3 g2((M + 127) / 128, 2), g1((M + 127) / 128, 1);

    // --- layer 0: 128 -> 256, relu ---
    aggregate_kernel<128><<<agg_blocks, 256>>>(0, M);
    gemm_mma<256, 256, true, true><<<g2, 256>>>(0, b0, nullptr, 1, 0, M);

    // --- layer 1: 256 -> 256, relu ---
    aggregate_kernel<256><<<agg_blocks, 256>>>(1, M);
    gemm_mma<512, 256, true, true><<<g2, 256>>>(1, b1, nullptr, 2, 65536, M);

    // --- layer 2: 256 -> 128, no act ---
    aggregate_kernel<256><<<agg_blocks, 256>>>(2, M);
    gemm_mma<512, 128, false, false><<<g1, 256>>>(2, b2, out, 0, 196608, M);
}

// round 10
// speedup vs baseline: 3.6594x; 1.1492x over previous
#include <cuda_runtime.h>
#include <cuda_fp16.h>
#include <cstdint>

#define NN 100000
#define NE 1600000

// ---------------- device scratch (allocation-free; ONLY touched from device code) ----------------
__device__ int   g_degi[NN];
__device__ int   g_rowptr[NN + 1];
__device__ int   g_cursor[NN];
__device__ int   g_adj[NE];
__device__ int   g_rtmp[NN];
__device__ int   g_bsum[128];
__device__ __align__(16) float  g_invdeg[NN];
// fp16 activations
__device__ __align__(16) __half g_x16[(size_t)NN * 128];
__device__ __align__(16) __half g_h116[(size_t)NN * 256];   // h1; reused as P in layer 2
__device__ __align__(16) __half g_h216[(size_t)NN * 256];
__device__ __align__(16) __half g_agg16[(size_t)NN * 256];
// fp16 weights: L0 [256][256]@0, L1 [256][512]@65536, L2 packed [256][256]@196608
__device__ __align__(16) __half g_wf[262144];

// fp16 plane selectors: 0 = g_x16, 1 = g_h116, 2 = g_h216
__device__ __forceinline__ const __half* sel_h(int sel) {
    if (sel == 1) return g_h116;
    if (sel == 2) return g_h216;
    return g_x16;
}

// ---------------- helpers ----------------
__device__ __forceinline__ void hacc(uint32_t u, float& a, float& b) {
    __half2 t = *reinterpret_cast<__half2*>(&u);
    float2 f = __half22float2(t);
    a += f.x; b += f.y;
}
__device__ __forceinline__ uint32_t packh2(float a, float b) {
    __half2 t = __floats2half2_rn(a, b);
    return *reinterpret_cast<uint32_t*>(&t);
}
__device__ __forceinline__ uint32_t smem_u32(const void* p) {
    uint32_t r;
    asm("{ .reg .u64 t; cvta.to.shared.u64 t, %1; cvt.u32.u64 %0, t; }" : "=r"(r) : "l"(p));
    return r;
}
__device__ __forceinline__ void ldmx4(uint32_t* r, uint32_t addr) {
    asm volatile("ldmatrix.sync.aligned.m8n8.x4.shared.b16 {%0,%1,%2,%3}, [%4];"
                 : "=r"(r[0]), "=r"(r[1]), "=r"(r[2]), "=r"(r[3]) : "r"(addr));
}
__device__ __forceinline__ void mma16816(float* c, const uint32_t* a, uint32_t b0, uint32_t b1) {
    asm volatile("mma.sync.aligned.m16n8k16.row.col.f32.f16.f16.f32 "
                 "{%0,%1,%2,%3}, {%4,%5,%6,%7}, {%8,%9}, {%0,%1,%2,%3};"
                 : "+f"(c[0]), "+f"(c[1]), "+f"(c[2]), "+f"(c[3])
                 : "r"(a[0]), "r"(a[1]), "r"(a[2]), "r"(a[3]), "r"(b0), "r"(b1));
}

// ---------------- CSR build ----------------
__global__ void zero_deg_kernel(int n) {
    int i = blockIdx.x * blockDim.x + threadIdx.x;
    if (i < n) g_degi[i] = 0;
}
__global__ void hist_kernel(const int* __restrict__ dst, int E, int n) {
    int i = blockIdx.x * blockDim.x + threadIdx.x;
    int stride = gridDim.x * blockDim.x;
    for (; i < E; i += stride) {
        int d = dst[i];
        if ((unsigned)d < (unsigned)n) atomicAdd(&g_degi[d], 1);
    }
}
// hierarchical scan: per-block excl scan + block totals
__global__ void scan1(int n) {
    __shared__ int ws[32];
    int b = blockIdx.x, tid = threadIdx.x;
    int lane = tid & 31, wid = tid >> 5;
    int i = b * 1024 + tid;
    int v = (i < n) ? g_degi[i] : 0;
    int s = v;
    #pragma unroll
    for (int off = 1; off < 32; off <<= 1) {
        int t = __shfl_up_sync(0xffffffffu, s, off);
        if (lane >= off) s += t;
    }
    if (lane == 31) ws[wid] = s;
    __syncthreads();
    if (wid == 0) {
        int t2 = (lane < 32) ? ws[lane] : 0;
        #pragma unroll
        for (int off = 1; off < 32; off <<= 1) {
            int t = __shfl_up_sync(0xffffffffu, t2, off);
            if (lane >= off) t2 += t;
        }
        ws[lane] = t2;
    }
    __syncthreads();
    int excl = s - v + (wid ? ws[wid - 1] : 0);
    if (i < n) g_rtmp[i] = excl;
    if (tid == 1023) g_bsum[b] = excl + v;
}
__global__ void scan2(int nb) {
    __shared__ int ws[4];
    int tid = threadIdx.x, lane = tid & 31, wid = tid >> 5;
    int v = (tid < nb) ? g_bsum[tid] : 0;
    int s = v;
    #pragma unroll
    for (int off = 1; off < 32; off <<= 1) {
        int t = __shfl_up_sync(0xffffffffu, s, off);
        if (lane >= off) s += t;
    }
    if (lane == 31) ws[wid] = s;
    __syncthreads();
    if (tid == 0) {
        int a = 0;
        #pragma unroll
        for (int q = 0; q < 4; q++) { int t = ws[q]; ws[q] = a; a += t; }
    }
    __syncthreads();
    int excl = s - v + ws[wid];
    if (tid < nb) g_bsum[tid] = excl;
}
__global__ void scan3(int n) {
    int i = blockIdx.x * blockDim.x + threadIdx.x;
    if (i < n) {
        int r = g_rtmp[i] + g_bsum[i >> 10];
        g_rowptr[i] = r;
        g_cursor[i] = r;
        if (i == n - 1) g_rowptr[n] = r + g_degi[i];
    }
}
__global__ void fill_kernel(const int* __restrict__ src, const int* __restrict__ dst, int E, int n) {
    int i = blockIdx.x * blockDim.x + threadIdx.x;
    int stride = gridDim.x * blockDim.x;
    for (; i < E; i += stride) {
        int d = dst[i], s = src[i];
        if ((unsigned)d < (unsigned)n && (unsigned)s < (unsigned)n) {
            int slot = atomicAdd(&g_cursor[d], 1);
            if ((unsigned)slot < (unsigned)NE) g_adj[slot] = s;
        }
    }
}
__global__ void invdeg_kernel(int n) {
    int i = blockIdx.x * blockDim.x + threadIdx.x;
    if (i < n) g_invdeg[i] = 1.0f / fmaxf((float)g_degi[i], 1.0f);
}

// ---------------- prep ----------------
// dual layout: W[N][2K] = rows n, cols [Wl(:,n) | Wr(:,n)]
__global__ void prep_w(const float* __restrict__ Wl, const float* __restrict__ Wr,
                       int K, int N, int off) {
    int K2 = 2 * K;
    int total = N * K2;
    for (int i = blockIdx.x * blockDim.x + threadIdx.x; i < total; i += gridDim.x * blockDim.x) {
        int n = i / K2, k = i % K2;
        float w = (k < K) ? Wl[(size_t)k * N + n] : Wr[(size_t)(k - K) * N + n];
        g_wf[(size_t)off + (size_t)n * K2 + k] = __float2half(w);
    }
}
// packed layout for L2: B[2*Nh][K]; row n<Nh -> Wl[:,n], else Wr[:,n-Nh]
__global__ void prep_w2(const float* __restrict__ Wl, const float* __restrict__ Wr,
                        int K, int Nh, int off) {
    int total = 2 * Nh * K;
    for (int i = blockIdx.x * blockDim.x + threadIdx.x; i < total; i += gridDim.x * blockDim.x) {
        int n = i / K, k = i % K;
        float w = (n < Nh) ? Wl[(size_t)k * Nh + n] : Wr[(size_t)k * Nh + (n - Nh)];
        g_wf[(size_t)off + (size_t)n * K + k] = __float2half(w);
    }
}
__global__ void conv_x(const float* __restrict__ x, int total4) {
    for (int i = blockIdx.x * blockDim.x + threadIdx.x; i < total4; i += gridDim.x * blockDim.x) {
        float4 v = *(const float4*)(x + (size_t)i * 4);
        *(uint2*)(g_x16 + (size_t)i * 4) = make_uint2(packh2(v.x, v.y), packh2(v.z, v.w));
    }
}

// ---------------- mean aggregation: fp16 gather, fp32 accumulate, fp16 write ----------------
template <int D>
__global__ void __launch_bounds__(256) aggregate_kernel(int src_sel, int n) {
    const __half* feat = sel_h(src_sel);
    int w = (blockIdx.x * blockDim.x + threadIdx.x) >> 5;
    int lane = threadIdx.x & 31;
    if (w >= n) return;
    int j = g_rowptr[w], end = g_rowptr[w + 1];

    if (D == 256) {
        float acc[8] = {0.f, 0.f, 0.f, 0.f, 0.f, 0.f, 0.f, 0.f};
        for (; j + 3 < end; j += 4) {
            int s0 = g_adj[j], s1 = g_adj[j + 1], s2 = g_adj[j + 2], s3 = g_adj[j + 3];
            uint4 va = *(const uint4*)(feat + (size_t)s0 * 256 + lane * 8);
            uint4 vb = *(const uint4*)(feat + (size_t)s1 * 256 + lane * 8);
            uint4 vc = *(const uint4*)(feat + (size_t)s2 * 256 + lane * 8);
            uint4 vd = *(const uint4*)(feat + (size_t)s3 * 256 + lane * 8);
            hacc(va.x, acc[0], acc[1]); hacc(va.y, acc[2], acc[3]);
            hacc(va.z, acc[4], acc[5]); hacc(va.w, acc[6], acc[7]);
            hacc(vb.x, acc[0], acc[1]); hacc(vb.y, acc[2], acc[3]);
            hacc(vb.z, acc[4], acc[5]); hacc(vb.w, acc[6], acc[7]);
            hacc(vc.x, acc[0], acc[1]); hacc(vc.y, acc[2], acc[3]);
            hacc(vc.z, acc[4], acc[5]); hacc(vc.w, acc[6], acc[7]);
            hacc(vd.x, acc[0], acc[1]); hacc(vd.y, acc[2], acc[3]);
            hacc(vd.z, acc[4], acc[5]); hacc(vd.w, acc[6], acc[7]);
        }
        for (; j < end; j++) {
            int s0 = g_adj[j];
            uint4 va = *(const uint4*)(feat + (size_t)s0 * 256 + lane * 8);
            hacc(va.x, acc[0], acc[1]); hacc(va.y, acc[2], acc[3]);
            hacc(va.z, acc[4], acc[5]); hacc(va.w, acc[6], acc[7]);
        }
        float sc = g_invdeg[w];
        uint4 o;
        o.x = packh2(acc[0] * sc, acc[1] * sc);
        o.y = packh2(acc[2] * sc, acc[3] * sc);
        o.z = packh2(acc[4] * sc, acc[5] * sc);
        o.w = packh2(acc[6] * sc, acc[7] * sc);
        *(uint4*)(g_agg16 + (size_t)w * 256 + lane * 8) = o;
    } else {
        float acc[4] = {0.f, 0.f, 0.f, 0.f};
        for (; j + 3 < end; j += 4) {
            int s0 = g_adj[j], s1 = g_adj[j + 1], s2 = g_adj[j + 2], s3 = g_adj[j + 3];
            uint2 va = *(const uint2*)(feat + (size_t)s0 * 128 + lane * 4);
            uint2 vb = *(const uint2*)(feat + (size_t)s1 * 128 + lane * 4);
            uint2 vc = *(const uint2*)(feat + (size_t)s2 * 128 + lane * 4);
            uint2 vd = *(const uint2*)(feat + (size_t)s3 * 128 + lane * 4);
            hacc(va.x, acc[0], acc[1]); hacc(va.y, acc[2], acc[3]);
            hacc(vb.x, acc[0], acc[1]); hacc(vb.y, acc[2], acc[3]);
            hacc(vc.x, acc[0], acc[1]); hacc(vc.y, acc[2], acc[3]);
            hacc(vd.x, acc[0], acc[1]); hacc(vd.y, acc[2], acc[3]);
        }
        for (; j < end; j++) {
            int s0 = g_adj[j];
            uint2 va = *(const uint2*)(feat + (size_t)s0 * 128 + lane * 4);
            hacc(va.x, acc[0], acc[1]); hacc(va.y, acc[2], acc[3]);
        }
        float sc = g_invdeg[w];
        *(uint2*)(g_agg16 + (size_t)w * 128 + lane * 4) =
            make_uint2(packh2(acc[0] * sc, acc[1] * sc), packh2(acc[2] * sc, acc[3] * sc));
    }
}

// ---------------- final: out[w] += mean-gather of P (g_h116, D=128 fp16) ----------------
__global__ void __launch_bounds__(256) agg_add(float* __restrict__ out, int n) {
    int w = (blockIdx.x * blockDim.x + threadIdx.x) >> 5;
    int lane = threadIdx.x & 31;
    if (w >= n) return;
    int j = g_rowptr[w], end = g_rowptr[w + 1];
    float acc[4] = {0.f, 0.f, 0.f, 0.f};
    for (; j + 3 < end; j += 4) {
        int s0 = g_adj[j], s1 = g_adj[j + 1], s2 = g_adj[j + 2], s3 = g_adj[j + 3];
        uint2 va = *(const uint2*)(g_h116 + (size_t)s0 * 128 + lane * 4);
        uint2 vb = *(const uint2*)(g_h116 + (size_t)s1 * 128 + lane * 4);
        uint2 vc = *(const uint2*)(g_h116 + (size_t)s2 * 128 + lane * 4);
        uint2 vd = *(const uint2*)(g_h116 + (size_t)s3 * 128 + lane * 4);
        hacc(va.x, acc[0], acc[1]); hacc(va.y, acc[2], acc[3]);
        hacc(vb.x, acc[0], acc[1]); hacc(vb.y, acc[2], acc[3]);
        hacc(vc.x, acc[0], acc[1]); hacc(vc.y, acc[2], acc[3]);
        hacc(vd.x, acc[0], acc[1]); hacc(vd.y, acc[2], acc[3]);
    }
    for (; j < end; j++) {
        int s0 = g_adj[j];
        uint2 va = *(const uint2*)(g_h116 + (size_t)s0 * 128 + lane * 4);
        hacc(va.x, acc[0], acc[1]); hacc(va.y, acc[2], acc[3]);
    }
    float sc = g_invdeg[w];
    float4* op = (float4*)(out + (size_t)w * 128 + lane * 4);
    float4 cur = *op;
    cur.x += acc[0] * sc; cur.y += acc[1] * sc;
    cur.z += acc[2] * sc; cur.w += acc[3] * sc;
    *op = cur;
}

// ---------------- tensor-core GEMM (fp16, single pass) ----------------
// DUAL:  out = act([agg16 | Ax] @ W + b), A halves stride KA/2.
// !DUAL: out = Ax @ W (+b per OUTMODE), A stride KA.
// OUTMODE: 0 = fp32 out_ext (+bias), 1 = fp16 plane out_sel (+bias),
//          2 = split: blockIdx.y==0 -> P fp16 to g_h116 (no bias), ==1 -> fp32 out_ext (+bias)
template <int KA, int N, bool DUAL, bool RELU, int OUTMODE>
__global__ void __launch_bounds__(256) gemm_mma(
    int x_sel, const float* __restrict__ bias,
    float* __restrict__ out_ext, int out_sel, int wboff, int M) {
    __shared__ __half sA[128 * 40];
    __shared__ __half sB[128 * 40];

    const __half* Ax = sel_h(x_sel);
    constexpr int ASTRIDE = DUAL ? KA / 2 : KA;
    constexpr int CHUNKS = KA / 32;

    int tid = threadIdx.x;
    int wid = tid >> 5, lane = tid & 31;
    int bm = blockIdx.x * 128, bn = blockIdx.y * 128;
    int wm = (wid & 3) * 32;
    int wn = (wid >> 2) * 64;

    float acc[2][8][4];
    #pragma unroll
    for (int i = 0; i < 2; i++)
        #pragma unroll
        for (int j = 0; j < 8; j++)
            #pragma unroll
            for (int q = 0; q < 4; q++) acc[i][j][q] = 0.f;

    int lr = tid >> 1, lc = (tid & 1) * 16;
    int arow = bm + lr; if (arow >= M) arow = M - 1;
    const __half* wb = g_wf + wboff;

    uint4 ua[2], ub[2];
    {
        const __half* ap = (DUAL ? g_agg16 : Ax) + (size_t)arow * ASTRIDE + lc;
        ua[0] = *(const uint4*)ap; ua[1] = *(const uint4*)(ap + 8);
        const __half* bp = wb + (size_t)(bn + lr) * KA + lc;
        ub[0] = *(const uint4*)bp; ub[1] = *(const uint4*)(bp + 8);
    }

    #pragma unroll 1
    for (int c = 0; c < CHUNKS; c++) {
        *(uint4*)&sA[lr * 40 + lc]     = ua[0];
        *(uint4*)&sA[lr * 40 + lc + 8] = ua[1];
        *(uint4*)&sB[lr * 40 + lc]     = ub[0];
        *(uint4*)&sB[lr * 40 + lc + 8] = ub[1];
        __syncthreads();

        if (c + 1 < CHUNKS) {
            int kk = (c + 1) * 32;
            const __half* Asrc;
            int col0;
            if (DUAL) {
                constexpr int K = KA / 2;
                Asrc = (kk < K) ? g_agg16 : Ax;
                col0 = (kk < K) ? kk : (kk - K);
            } else {
                Asrc = Ax; col0 = kk;
            }
            const __half* ap = Asrc + (size_t)arow * ASTRIDE + col0 + lc;
            ua[0] = *(const uint4*)ap; ua[1] = *(const uint4*)(ap + 8);
            const __half* bp = wb + (size_t)(bn + lr) * KA + kk + lc;
            ub[0] = *(const uint4*)bp; ub[1] = *(const uint4*)(bp + 8);
        }

        #pragma unroll
        for (int ks = 0; ks < 2; ks++) {
            int lrow = lane & 15, lcolsel = (lane >> 4) * 8 + ks * 16;
            uint32_t a[2][4];
            #pragma unroll
            for (int mi = 0; mi < 2; mi++)
                ldmx4(a[mi], smem_u32(&sA[(wm + mi * 16 + lrow) * 40 + lcolsel]));
            #pragma unroll
            for (int nj = 0; nj < 4; nj++) {
                uint32_t bf[4];
                ldmx4(bf, smem_u32(&sB[(wn + nj * 16 + lrow) * 40 + lcolsel]));
                #pragma unroll
                for (int mi = 0; mi < 2; mi++) {
                    mma16816(acc[mi][nj * 2],     a[mi], bf[0], bf[2]);
                    mma16816(acc[mi][nj * 2 + 1], a[mi], bf[1], bf[3]);
                }
            }
        }
        __syncthreads();
    }

    // ---- epilogue ----
    int tg = lane & 3, g = lane >> 2;
    __half* out16 = (out_sel == 1) ? g_h116 : g_h216;
    bool isP = (OUTMODE == 2) && (blockIdx.y == 0);
    #pragma unroll
    for (int mi = 0; mi < 2; mi++) {
        int r0 = bm + wm + mi * 16 + g;
        int r1 = r0 + 8;
        #pragma unroll
        for (int ni = 0; ni < 8; ni++) {
            int col = bn + wn + ni * 8 + tg * 2;
            int colb = (OUTMODE == 2) ? (col & 127) : col;
            float b0 = isP ? 0.f : __ldg(&bias[colb]);
            float b1 = isP ? 0.f : __ldg(&bias[colb + 1]);
            float v0 = acc[mi][ni][0] + b0, v1 = acc[mi][ni][1] + b1;
            float v2 = acc[mi][ni][2] + b0, v3 = acc[mi][ni][3] + b1;
            if (RELU) {
                v0 = fmaxf(v0, 0.f); v1 = fmaxf(v1, 0.f);
                v2 = fmaxf(v2, 0.f); v3 = fmaxf(v3, 0.f);
            }
            if (OUTMODE == 0) {
                if (r0 < M) *(float2*)(out_ext + (size_t)r0 * N + col) = make_float2(v0, v1);
                if (r1 < M) *(float2*)(out_ext + (size_t)r1 * N + col) = make_float2(v2, v3);
            } else if (OUTMODE == 1) {
                if (r0 < M) *(uint32_t*)(out16 + (size_t)r0 * N + col) = packh2(v0, v1);
                if (r1 < M) *(uint32_t*)(out16 + (size_t)r1 * N + col) = packh2(v2, v3);
            } else {
                if (isP) {  // P -> g_h116, stride 128, fp16, no bias
                    if (r0 < M) *(uint32_t*)(g_h116 + (size_t)r0 * 128 + colb) = packh2(v0, v1);
                    if (r1 < M) *(uint32_t*)(g_h116 + (size_t)r1 * 128 + colb) = packh2(v2, v3);
                } else {    // Q + b2 -> fp32 out, stride 128
                    if (r0 < M) *(float2*)(out_ext + (size_t)r0 * 128 + colb) = make_float2(v0, v1);
                    if (r1 < M) *(float2*)(out_ext + (size_t)r1 * 128 + colb) = make_float2(v2, v3);
                }
            }
        }
    }
}

// ---------------- launch ----------------
extern "C" void kernel_launch(void* const* d_in, const int* in_sizes, int n_in,
                              void* d_out, int out_size) {
    const float* x   = (const float*)d_in[0];
    const int*   ei  = (const int*)d_in[1];     // int32 edge_index [2, E]
    const float* Wl0 = (const float*)d_in[2];
    const float* b0  = (const float*)d_in[3];
    const float* Wr0 = (const float*)d_in[4];
    const float* Wl1 = (const float*)d_in[5];
    const float* b1  = (const float*)d_in[6];
    const float* Wr1 = (const float*)d_in[7];
    const float* Wl2 = (const float*)d_in[8];
    const float* b2  = (const float*)d_in[9];
    const float* Wr2 = (const float*)d_in[10];
    float* out = (float*)d_out;

    const int E = in_sizes[1] / 2;
    const int M = in_sizes[0] / 128;
    const int* src = ei;
    const int* dst = ei + E;
    const int nb = (M + 1023) / 1024;

    // --- CSR build (hierarchical scan) ---
    zero_deg_kernel<<<(M + 255) / 256, 256>>>(M);
    hist_kernel<<<2048, 256>>>(dst, E, M);
    scan1<<<nb, 1024>>>(M);
    scan2<<<1, 128>>>(nb);
    scan3<<<(M + 255) / 256, 256>>>(M);
    fill_kernel<<<2048, 256>>>(src, dst, E, M);
    invdeg_kernel<<<(M + 255) / 256, 256>>>(M);

    // --- prep: fp16 weights + fp16 x ---
    prep_w<<<256, 256>>>(Wl0, Wr0, 128, 256, 0);
    prep_w<<<512, 256>>>(Wl1, Wr1, 256, 256, 65536);
    prep_w2<<<256, 256>>>(Wl2, Wr2, 256, 128, 196608);
    conv_x<<<2048, 256>>>(x, M * 32);

    const int agg_blocks = (M * 32 + 255) / 256;
    dim3 g2((M + 127) / 128, 2);

    // --- layer 0: 128 -> 256, relu ---
    aggregate_kernel<128><<<agg_blocks, 256>>>(0, M);
    gemm_mma<256, 256, true, true, 1><<<g2, 256>>>(0, b0, nullptr, 1, 0, M);

    // --- layer 1: 256 -> 256, relu ---
    aggregate_kernel<256><<<agg_blocks, 256>>>(1, M);
    gemm_mma<512, 256, true, true, 1><<<g2, 256>>>(1, b1, nullptr, 2, 65536, M);

    // --- layer 2 (commuted): [P|Q] = h2 @ [Wl2|Wr2]; out = Q + b2; out += mean-gather(P) ---
    gemm_mma<256, 256, false, false, 2><<<g2, 256>>>(2, b2, out, 0, 196608, M);
    agg_add<<<agg_blocks, 256>>>(out, M);
}

// round 11
// speedup vs baseline: 3.9018x; 1.0662x over previous
#include <cuda_runtime.h>
#include <cuda_fp16.h>
#include <cstdint>

#define NN 100000
#define NE 1600000

// ---------------- device scratch (allocation-free; ONLY touched from device code) ----------------
__device__ int   g_degi[NN];
__device__ int   g_rowptr[NN + 1];
__device__ int   g_cursor[NN];
__device__ int   g_adj[NE];
__device__ int   g_rtmp[NN];
__device__ int   g_bsum[128];
__device__ __align__(16) float  g_invdeg[NN];
// fp16 activations
__device__ __align__(16) __half g_x16[(size_t)NN * 128];
__device__ __align__(16) __half g_h116[(size_t)NN * 256];   // h1; reused as P in layer 2
__device__ __align__(16) __half g_h216[(size_t)NN * 256];
__device__ __align__(16) __half g_agg16[(size_t)NN * 256];
// fp16 weights: L0 [256][256]@0, L1 [256][512]@65536, L2 packed [256][256]@196608
__device__ __align__(16) __half g_wf[262144];

// fp16 plane selectors: 0 = g_x16, 1 = g_h116, 2 = g_h216
__device__ __forceinline__ const __half* sel_h(int sel) {
    if (sel == 1) return g_h116;
    if (sel == 2) return g_h216;
    return g_x16;
}

// ---------------- helpers ----------------
__device__ __forceinline__ void hacc(uint32_t u, float& a, float& b) {
    __half2 t = *reinterpret_cast<__half2*>(&u);
    float2 f = __half22float2(t);
    a += f.x; b += f.y;
}
__device__ __forceinline__ uint32_t packh2(float a, float b) {
    __half2 t = __floats2half2_rn(a, b);
    return *reinterpret_cast<uint32_t*>(&t);
}
__device__ __forceinline__ uint32_t smem_u32(const void* p) {
    uint32_t r;
    asm("{ .reg .u64 t; cvta.to.shared.u64 t, %1; cvt.u32.u64 %0, t; }" : "=r"(r) : "l"(p));
    return r;
}
__device__ __forceinline__ void cp16(void* smem, const void* g) {
    asm volatile("cp.async.cg.shared.global [%0], [%1], 16;"
                 :: "r"(smem_u32(smem)), "l"(g) : "memory");
}
#define CP_COMMIT() asm volatile("cp.async.commit_group;" ::: "memory")
template <int Nw>
__device__ __forceinline__ void cp_wait() {
    asm volatile("cp.async.wait_group %0;" :: "n"(Nw) : "memory");
}
__device__ __forceinline__ void ldmx4(uint32_t* r, uint32_t addr) {
    asm volatile("ldmatrix.sync.aligned.m8n8.x4.shared.b16 {%0,%1,%2,%3}, [%4];"
                 : "=r"(r[0]), "=r"(r[1]), "=r"(r[2]), "=r"(r[3]) : "r"(addr));
}
__device__ __forceinline__ void mma16816(float* c, const uint32_t* a, uint32_t b0, uint32_t b1) {
    asm volatile("mma.sync.aligned.m16n8k16.row.col.f32.f16.f16.f32 "
                 "{%0,%1,%2,%3}, {%4,%5,%6,%7}, {%8,%9}, {%0,%1,%2,%3};"
                 : "+f"(c[0]), "+f"(c[1]), "+f"(c[2]), "+f"(c[3])
                 : "r"(a[0]), "r"(a[1]), "r"(a[2]), "r"(a[3]), "r"(b0), "r"(b1));
}

// ---------------- CSR build ----------------
__global__ void zero_deg_kernel(int n) {
    int i = blockIdx.x * blockDim.x + threadIdx.x;
    if (i < n) g_degi[i] = 0;
}
__global__ void hist_kernel(const int* __restrict__ dst, int E, int n) {
    int i = blockIdx.x * blockDim.x + threadIdx.x;
    int stride = gridDim.x * blockDim.x;
    for (; i < E; i += stride) {
        int d = dst[i];
        if ((unsigned)d < (unsigned)n) atomicAdd(&g_degi[d], 1);
    }
}
// hierarchical scan: per-block excl scan + block totals
__global__ void scan1(int n) {
    __shared__ int ws[32];
    int b = blockIdx.x, tid = threadIdx.x;
    int lane = tid & 31, wid = tid >> 5;
    int i = b * 1024 + tid;
    int v = (i < n) ? g_degi[i] : 0;
    int s = v;
    #pragma unroll
    for (int off = 1; off < 32; off <<= 1) {
        int t = __shfl_up_sync(0xffffffffu, s, off);
        if (lane >= off) s += t;
    }
    if (lane == 31) ws[wid] = s;
    __syncthreads();
    if (wid == 0) {
        int t2 = (lane < 32) ? ws[lane] : 0;
        #pragma unroll
        for (int off = 1; off < 32; off <<= 1) {
            int t = __shfl_up_sync(0xffffffffu, t2, off);
            if (lane >= off) t2 += t;
        }
        ws[lane] = t2;
    }
    __syncthreads();
    int excl = s - v + (wid ? ws[wid - 1] : 0);
    if (i < n) g_rtmp[i] = excl;
    if (tid == 1023) g_bsum[b] = excl + v;
}
__global__ void scan2(int nb) {
    __shared__ int ws[4];
    int tid = threadIdx.x, lane = tid & 31, wid = tid >> 5;
    int v = (tid < nb) ? g_bsum[tid] : 0;
    int s = v;
    #pragma unroll
    for (int off = 1; off < 32; off <<= 1) {
        int t = __shfl_up_sync(0xffffffffu, s, off);
        if (lane >= off) s += t;
    }
    if (lane == 31) ws[wid] = s;
    __syncthreads();
    if (tid == 0) {
        int a = 0;
        #pragma unroll
        for (int q = 0; q < 4; q++) { int t = ws[q]; ws[q] = a; a += t; }
    }
    __syncthreads();
    int excl = s - v + ws[wid];
    if (tid < nb) g_bsum[tid] = excl;
}
// scan3 + invdeg fused
__global__ void scan3(int n) {
    int i = blockIdx.x * blockDim.x + threadIdx.x;
    if (i < n) {
        int deg = g_degi[i];
        int r = g_rtmp[i] + g_bsum[i >> 10];
        g_rowptr[i] = r;
        g_cursor[i] = r;
        g_invdeg[i] = 1.0f / fmaxf((float)deg, 1.0f);
        if (i == n - 1) g_rowptr[n] = r + deg;
    }
}
__global__ void fill_kernel(const int* __restrict__ src, const int* __restrict__ dst, int E, int n) {
    int i = blockIdx.x * blockDim.x + threadIdx.x;
    int stride = gridDim.x * blockDim.x;
    for (; i < E; i += stride) {
        int d = dst[i], s = src[i];
        if ((unsigned)d < (unsigned)n && (unsigned)s < (unsigned)n) {
            int slot = atomicAdd(&g_cursor[d], 1);
            if ((unsigned)slot < (unsigned)NE) g_adj[slot] = s;
        }
    }
}

// ---------------- prep: all 3 layers' fp16 weights in one kernel ----------------
// L0 dual [256][256]@0; L1 dual [256][512]@65536; L2 packed [256][256]@196608
__global__ void prep_w_all(const float* __restrict__ Wl0, const float* __restrict__ Wr0,
                           const float* __restrict__ Wl1, const float* __restrict__ Wr1,
                           const float* __restrict__ Wl2, const float* __restrict__ Wr2) {
    for (int i = blockIdx.x * blockDim.x + threadIdx.x; i < 262144; i += gridDim.x * blockDim.x) {
        float w;
        if (i < 65536) {            // L0: K=128, N=256, K2=256
            int n = i >> 8, k = i & 255;
            w = (k < 128) ? Wl0[(size_t)k * 256 + n] : Wr0[(size_t)(k - 128) * 256 + n];
        } else if (i < 196608) {    // L1: K=256, N=256, K2=512
            int j = i - 65536;
            int n = j >> 9, k = j & 511;
            w = (k < 256) ? Wl1[(size_t)k * 256 + n] : Wr1[(size_t)(k - 256) * 256 + n];
        } else {                    // L2 packed: rows 0-127 Wl2 cols, 128-255 Wr2 cols; K=256
            int j = i - 196608;
            int n = j >> 8, k = j & 255;
            w = (n < 128) ? Wl2[(size_t)k * 128 + n] : Wr2[(size_t)k * 128 + (n - 128)];
        }
        g_wf[i] = __float2half(w);
    }
}
__global__ void conv_x(const float* __restrict__ x, int total4) {
    for (int i = blockIdx.x * blockDim.x + threadIdx.x; i < total4; i += gridDim.x * blockDim.x) {
        float4 v = *(const float4*)(x + (size_t)i * 4);
        *(uint2*)(g_x16 + (size_t)i * 4) = make_uint2(packh2(v.x, v.y), packh2(v.z, v.w));
    }
}

// ---------------- mean aggregation: fp16 gather, fp32 accumulate, fp16 write ----------------
template <int D>
__global__ void __launch_bounds__(256) aggregate_kernel(int src_sel, int n) {
    const __half* feat = sel_h(src_sel);
    int w = (blockIdx.x * blockDim.x + threadIdx.x) >> 5;
    int lane = threadIdx.x & 31;
    if (w >= n) return;
    int j = g_rowptr[w], end = g_rowptr[w + 1];

    if (D == 256) {
        float acc[8] = {0.f, 0.f, 0.f, 0.f, 0.f, 0.f, 0.f, 0.f};
        for (; j + 3 < end; j += 4) {
            int s0 = g_adj[j], s1 = g_adj[j + 1], s2 = g_adj[j + 2], s3 = g_adj[j + 3];
            uint4 va = *(const uint4*)(feat + (size_t)s0 * 256 + lane * 8);
            uint4 vb = *(const uint4*)(feat + (size_t)s1 * 256 + lane * 8);
            uint4 vc = *(const uint4*)(feat + (size_t)s2 * 256 + lane * 8);
            uint4 vd = *(const uint4*)(feat + (size_t)s3 * 256 + lane * 8);
            hacc(va.x, acc[0], acc[1]); hacc(va.y, acc[2], acc[3]);
            hacc(va.z, acc[4], acc[5]); hacc(va.w, acc[6], acc[7]);
            hacc(vb.x, acc[0], acc[1]); hacc(vb.y, acc[2], acc[3]);
            hacc(vb.z, acc[4], acc[5]); hacc(vb.w, acc[6], acc[7]);
            hacc(vc.x, acc[0], acc[1]); hacc(vc.y, acc[2], acc[3]);
            hacc(vc.z, acc[4], acc[5]); hacc(vc.w, acc[6], acc[7]);
            hacc(vd.x, acc[0], acc[1]); hacc(vd.y, acc[2], acc[3]);
            hacc(vd.z, acc[4], acc[5]); hacc(vd.w, acc[6], acc[7]);
        }
        for (; j < end; j++) {
            int s0 = g_adj[j];
            uint4 va = *(const uint4*)(feat + (size_t)s0 * 256 + lane * 8);
            hacc(va.x, acc[0], acc[1]); hacc(va.y, acc[2], acc[3]);
            hacc(va.z, acc[4], acc[5]); hacc(va.w, acc[6], acc[7]);
        }
        float sc = g_invdeg[w];
        uint4 o;
        o.x = packh2(acc[0] * sc, acc[1] * sc);
        o.y = packh2(acc[2] * sc, acc[3] * sc);
        o.z = packh2(acc[4] * sc, acc[5] * sc);
        o.w = packh2(acc[6] * sc, acc[7] * sc);
        *(uint4*)(g_agg16 + (size_t)w * 256 + lane * 8) = o;
    } else {
        float acc[4] = {0.f, 0.f, 0.f, 0.f};
        for (; j + 3 < end; j += 4) {
            int s0 = g_adj[j], s1 = g_adj[j + 1], s2 = g_adj[j + 2], s3 = g_adj[j + 3];
            uint2 va = *(const uint2*)(feat + (size_t)s0 * 128 + lane * 4);
            uint2 vb = *(const uint2*)(feat + (size_t)s1 * 128 + lane * 4);
            uint2 vc = *(const uint2*)(feat + (size_t)s2 * 128 + lane * 4);
            uint2 vd = *(const uint2*)(feat + (size_t)s3 * 128 + lane * 4);
            hacc(va.x, acc[0], acc[1]); hacc(va.y, acc[2], acc[3]);
            hacc(vb.x, acc[0], acc[1]); hacc(vb.y, acc[2], acc[3]);
            hacc(vc.x, acc[0], acc[1]); hacc(vc.y, acc[2], acc[3]);
            hacc(vd.x, acc[0], acc[1]); hacc(vd.y, acc[2], acc[3]);
        }
        for (; j < end; j++) {
            int s0 = g_adj[j];
            uint2 va = *(const uint2*)(feat + (size_t)s0 * 128 + lane * 4);
            hacc(va.x, acc[0], acc[1]); hacc(va.y, acc[2], acc[3]);
        }
        float sc = g_invdeg[w];
        *(uint2*)(g_agg16 + (size_t)w * 128 + lane * 4) =
            make_uint2(packh2(acc[0] * sc, acc[1] * sc), packh2(acc[2] * sc, acc[3] * sc));
    }
}

// ---------------- final: out[w] += mean-gather of P (g_h116, D=128 fp16) ----------------
__global__ void __launch_bounds__(256) agg_add(float* __restrict__ out, int n) {
    int w = (blockIdx.x * blockDim.x + threadIdx.x) >> 5;
    int lane = threadIdx.x & 31;
    if (w >= n) return;
    int j = g_rowptr[w], end = g_rowptr[w + 1];
    float acc[4] = {0.f, 0.f, 0.f, 0.f};
    for (; j + 3 < end; j += 4) {
        int s0 = g_adj[j], s1 = g_adj[j + 1], s2 = g_adj[j + 2], s3 = g_adj[j + 3];
        uint2 va = *(const uint2*)(g_h116 + (size_t)s0 * 128 + lane * 4);
        uint2 vb = *(const uint2*)(g_h116 + (size_t)s1 * 128 + lane * 4);
        uint2 vc = *(const uint2*)(g_h116 + (size_t)s2 * 128 + lane * 4);
        uint2 vd = *(const uint2*)(g_h116 + (size_t)s3 * 128 + lane * 4);
        hacc(va.x, acc[0], acc[1]); hacc(va.y, acc[2], acc[3]);
        hacc(vb.x, acc[0], acc[1]); hacc(vb.y, acc[2], acc[3]);
        hacc(vc.x, acc[0], acc[1]); hacc(vc.y, acc[2], acc[3]);
        hacc(vd.x, acc[0], acc[1]); hacc(vd.y, acc[2], acc[3]);
    }
    for (; j < end; j++) {
        int s0 = g_adj[j];
        uint2 va = *(const uint2*)(g_h116 + (size_t)s0 * 128 + lane * 4);
        hacc(va.x, acc[0], acc[1]); hacc(va.y, acc[2], acc[3]);
    }
    float sc = g_invdeg[w];
    float4* op = (float4*)(out + (size_t)w * 128 + lane * 4);
    float4 cur = *op;
    cur.x += acc[0] * sc; cur.y += acc[1] * sc;
    cur.z += acc[2] * sc; cur.w += acc[3] * sc;
    *op = cur;
}

// ---------------- tensor-core GEMM (fp16, cp.async 2-stage pipeline) ----------------
// DUAL:  out = act([agg16 | Ax] @ W + b), A halves stride KA/2.
// !DUAL: out = Ax @ W (+b per OUTMODE), A stride KA.
// OUTMODE: 0 = fp32 out_ext (+bias), 1 = fp16 plane out_sel (+bias),
//          2 = split: blockIdx.y==0 -> P fp16 to g_h116 (no bias), ==1 -> fp32 out_ext (+bias)
template <int KA, int N, bool DUAL, bool RELU, int OUTMODE>
__global__ void __launch_bounds__(256) gemm_mma(
    int x_sel, const float* __restrict__ bias,
    float* __restrict__ out_ext, int out_sel, int wboff, int M) {
    __shared__ __align__(16) __half sA[2][128 * 40];
    __shared__ __align__(16) __half sB[2][128 * 40];

    const __half* Ax = sel_h(x_sel);
    constexpr int ASTRIDE = DUAL ? KA / 2 : KA;
    constexpr int CHUNKS = KA / 32;

    int tid = threadIdx.x;
    int wid = tid >> 5, lane = tid & 31;
    int bm = blockIdx.x * 128, bn = blockIdx.y * 128;
    int wm = (wid & 3) * 32;
    int wn = (wid >> 2) * 64;

    float acc[2][8][4];
    #pragma unroll
    for (int i = 0; i < 2; i++)
        #pragma unroll
        for (int j = 0; j < 8; j++)
            #pragma unroll
            for (int q = 0; q < 4; q++) acc[i][j][q] = 0.f;

    int lr = tid >> 1, lc = (tid & 1) * 16;
    int arow = bm + lr; if (arow >= M) arow = M - 1;
    const __half* wb = g_wf + wboff;

    auto issue = [&](int c, int buf) {
        int kk = c * 32;
        const __half* ap;
        if (DUAL) {
            constexpr int K = KA / 2;
            const __half* Asrc = (kk < K) ? g_agg16 : Ax;
            int col0 = (kk < K) ? kk : (kk - K);
            ap = Asrc + (size_t)arow * ASTRIDE + col0 + lc;
        } else {
            ap = Ax + (size_t)arow * ASTRIDE + kk + lc;
        }
        cp16(&sA[buf][lr * 40 + lc], ap);
        cp16(&sA[buf][lr * 40 + lc + 8], ap + 8);
        const __half* bp = wb + (size_t)(bn + lr) * KA + kk + lc;
        cp16(&sB[buf][lr * 40 + lc], bp);
        cp16(&sB[buf][lr * 40 + lc + 8], bp + 8);
        CP_COMMIT();
    };

    issue(0, 0);

    #pragma unroll 1
    for (int c = 0; c < CHUNKS; c++) {
        int buf = c & 1;
        if (c + 1 < CHUNKS) {
            issue(c + 1, buf ^ 1);
            cp_wait<1>();
        } else {
            cp_wait<0>();
        }
        __syncthreads();

        #pragma unroll
        for (int ks = 0; ks < 2; ks++) {
            int lrow = lane & 15, lcolsel = (lane >> 4) * 8 + ks * 16;
            uint32_t a[2][4];
            #pragma unroll
            for (int mi = 0; mi < 2; mi++)
                ldmx4(a[mi], smem_u32(&sA[buf][(wm + mi * 16 + lrow) * 40 + lcolsel]));
            #pragma unroll
            for (int nj = 0; nj < 4; nj++) {
                uint32_t bf[4];
                ldmx4(bf, smem_u32(&sB[buf][(wn + nj * 16 + lrow) * 40 + lcolsel]));
                #pragma unroll
                for (int mi = 0; mi < 2; mi++) {
                    mma16816(acc[mi][nj * 2],     a[mi], bf[0], bf[2]);
                    mma16816(acc[mi][nj * 2 + 1], a[mi], bf[1], bf[3]);
                }
            }
        }
        __syncthreads();   // protect buf before it is re-issued at iteration c+1
    }

    // ---- epilogue ----
    int tg = lane & 3, g = lane >> 2;
    __half* out16 = (out_sel == 1) ? g_h116 : g_h216;
    bool isP = (OUTMODE == 2) && (blockIdx.y == 0);
    #pragma unroll
    for (int mi = 0; mi < 2; mi++) {
        int r0 = bm + wm + mi * 16 + g;
        int r1 = r0 + 8;
        #pragma unroll
        for (int ni = 0; ni < 8; ni++) {
            int col = bn + wn + ni * 8 + tg * 2;
            int colb = (OUTMODE == 2) ? (col & 127) : col;
            float b0 = isP ? 0.f : __ldg(&bias[colb]);
            float b1 = isP ? 0.f : __ldg(&bias[colb + 1]);
            float v0 = acc[mi][ni][0] + b0, v1 = acc[mi][ni][1] + b1;
            float v2 = acc[mi][ni][2] + b0, v3 = acc[mi][ni][3] + b1;
            if (RELU) {
                v0 = fmaxf(v0, 0.f); v1 = fmaxf(v1, 0.f);
                v2 = fmaxf(v2, 0.f); v3 = fmaxf(v3, 0.f);
            }
            if (OUTMODE == 0) {
                if (r0 < M) *(float2*)(out_ext + (size_t)r0 * N + col) = make_float2(v0, v1);
                if (r1 < M) *(float2*)(out_ext + (size_t)r1 * N + col) = make_float2(v2, v3);
            } else if (OUTMODE == 1) {
                if (r0 < M) *(uint32_t*)(out16 + (size_t)r0 * N + col) = packh2(v0, v1);
                if (r1 < M) *(uint32_t*)(out16 + (size_t)r1 * N + col) = packh2(v2, v3);
            } else {
                if (isP) {  // P -> g_h116, stride 128, fp16, no bias
                    if (r0 < M) *(uint32_t*)(g_h116 + (size_t)r0 * 128 + colb) = packh2(v0, v1);
                    if (r1 < M) *(uint32_t*)(g_h116 + (size_t)r1 * 128 + colb) = packh2(v2, v3);
                } else {    // Q + b2 -> fp32 out, stride 128
                    if (r0 < M) *(float2*)(out_ext + (size_t)r0 * 128 + colb) = make_float2(v0, v1);
                    if (r1 < M) *(float2*)(out_ext + (size_t)r1 * 128 + colb) = make_float2(v2, v3);
                }
            }
        }
    }
}

// ---------------- launch ----------------
extern "C" void kernel_launch(void* const* d_in, const int* in_sizes, int n_in,
                              void* d_out, int out_size) {
    const float* x   = (const float*)d_in[0];
    const int*   ei  = (const int*)d_in[1];     // int32 edge_index [2, E]
    const float* Wl0 = (const float*)d_in[2];
    const float* b0  = (const float*)d_in[3];
    const float* Wr0 = (const float*)d_in[4];
    const float* Wl1 = (const float*)d_in[5];
    const float* b1  = (const float*)d_in[6];
    const float* Wr1 = (const float*)d_in[7];
    const float* Wl2 = (const float*)d_in[8];
    const float* b2  = (const float*)d_in[9];
    const float* Wr2 = (const float*)d_in[10];
    float* out = (float*)d_out;

    const int E = in_sizes[1] / 2;
    const int M = in_sizes[0] / 128;
    const int* src = ei;
    const int* dst = ei + E;
    const int nb = (M + 1023) / 1024;

    // --- CSR build (hierarchical scan; invdeg fused into scan3) ---
    zero_deg_kernel<<<(M + 255) / 256, 256>>>(M);
    hist_kernel<<<2048, 256>>>(dst, E, M);
    scan1<<<nb, 1024>>>(M);
    scan2<<<1, 128>>>(nb);
    scan3<<<(M + 255) / 256, 256>>>(M);
    fill_kernel<<<2048, 256>>>(src, dst, E, M);

    // --- prep: all fp16 weights in one kernel + fp16 x ---
    prep_w_all<<<1024, 256>>>(Wl0, Wr0, Wl1, Wr1, Wl2, Wr2);
    conv_x<<<2048, 256>>>(x, M * 32);

    const int agg_blocks = (M * 32 + 255) / 256;
    dim3 g2((M + 127) / 128, 2);

    // --- layer 0: 128 -> 256, relu ---
    aggregate_kernel<128><<<agg_blocks, 256>>>(0, M);
    gemm_mma<256, 256, true, true, 1><<<g2, 256>>>(0, b0, nullptr, 1, 0, M);

    // --- layer 1: 256 -> 256, relu ---
    aggregate_kernel<256><<<agg_blocks, 256>>>(1, M);
    gemm_mma<512, 256, true, true, 1><<<g2, 256>>>(1, b1, nullptr, 2, 65536, M);

    // --- layer 2 (commuted): [P|Q] = h2 @ [Wl2|Wr2]; out = Q + b2; out += mean-gather(P) ---
    gemm_mma<256, 256, false, false, 2><<<g2, 256>>>(2, b2, out, 0, 196608, M);
    agg_add<<<agg_blocks, 256>>>(out, M);
}

// round 12
// speedup vs baseline: 3.9393x; 1.0096x over previous
#include <cuda_runtime.h>
#include <cuda_fp16.h>
#include <cstdint>

#define NN 100000
#define NE 1600000

// ---------------- device scratch (allocation-free; ONLY touched from device code) ----------------
__device__ int   g_degi[NN];
__device__ int   g_rowptr[NN + 1];
__device__ int   g_cursor[NN];
__device__ int   g_adj[NE];
__device__ int   g_rtmp[NN];
__device__ int   g_bsum[128];
__device__ __align__(16) float  g_invdeg[NN];
// fp16 activations
__device__ __align__(16) __half g_x16[(size_t)NN * 128];
__device__ __align__(16) __half g_h116[(size_t)NN * 256];   // h1; reused as P in layer 2
__device__ __align__(16) __half g_h216[(size_t)NN * 256];
__device__ __align__(16) __half g_agg16[(size_t)NN * 256];
// fp16 weights: L0 [256][256]@0, L1 [256][512]@65536, L2 packed [256][256]@196608
__device__ __align__(16) __half g_wf[262144];

// fp16 plane selectors: 0 = g_x16, 1 = g_h116, 2 = g_h216
__device__ __forceinline__ const __half* sel_h(int sel) {
    if (sel == 1) return g_h116;
    if (sel == 2) return g_h216;
    return g_x16;
}

// ---------------- helpers ----------------
__device__ __forceinline__ void hacc(uint32_t u, float& a, float& b) {
    __half2 t = *reinterpret_cast<__half2*>(&u);
    float2 f = __half22float2(t);
    a += f.x; b += f.y;
}
__device__ __forceinline__ uint32_t packh2(float a, float b) {
    __half2 t = __floats2half2_rn(a, b);
    return *reinterpret_cast<uint32_t*>(&t);
}
__device__ __forceinline__ uint32_t smem_u32(const void* p) {
    uint32_t r;
    asm("{ .reg .u64 t; cvta.to.shared.u64 t, %1; cvt.u32.u64 %0, t; }" : "=r"(r) : "l"(p));
    return r;
}
__device__ __forceinline__ void cp16(uint32_t smem, const void* g) {
    asm volatile("cp.async.cg.shared.global [%0], [%1], 16;"
                 :: "r"(smem), "l"(g) : "memory");
}
#define CP_COMMIT() asm volatile("cp.async.commit_group;" ::: "memory")
template <int Nw>
__device__ __forceinline__ void cp_wait() {
    asm volatile("cp.async.wait_group %0;" :: "n"(Nw) : "memory");
}
__device__ __forceinline__ void ldmx4(uint32_t* r, uint32_t addr) {
    asm volatile("ldmatrix.sync.aligned.m8n8.x4.shared.b16 {%0,%1,%2,%3}, [%4];"
                 : "=r"(r[0]), "=r"(r[1]), "=r"(r[2]), "=r"(r[3]) : "r"(addr));
}
__device__ __forceinline__ void mma16816(float* c, const uint32_t* a, uint32_t b0, uint32_t b1) {
    asm volatile("mma.sync.aligned.m16n8k16.row.col.f32.f16.f16.f32 "
                 "{%0,%1,%2,%3}, {%4,%5,%6,%7}, {%8,%9}, {%0,%1,%2,%3};"
                 : "+f"(c[0]), "+f"(c[1]), "+f"(c[2]), "+f"(c[3])
                 : "r"(a[0]), "r"(a[1]), "r"(a[2]), "r"(a[3]), "r"(b0), "r"(b1));
}

// ---------------- CSR build ----------------
__global__ void zero_deg_kernel(int n) {
    int i = blockIdx.x * blockDim.x + threadIdx.x;
    if (i < n) g_degi[i] = 0;
}
__global__ void hist_kernel(const int* __restrict__ dst, int E, int n) {
    int i = blockIdx.x * blockDim.x + threadIdx.x;
    int stride = gridDim.x * blockDim.x;
    for (; i < E; i += stride) {
        int d = dst[i];
        if ((unsigned)d < (unsigned)n) atomicAdd(&g_degi[d], 1);
    }
}
// hierarchical scan: per-block excl scan + block totals
__global__ void scan1(int n) {
    __shared__ int ws[32];
    int b = blockIdx.x, tid = threadIdx.x;
    int lane = tid & 31, wid = tid >> 5;
    int i = b * 1024 + tid;
    int v = (i < n) ? g_degi[i] : 0;
    int s = v;
    #pragma unroll
    for (int off = 1; off < 32; off <<= 1) {
        int t = __shfl_up_sync(0xffffffffu, s, off);
        if (lane >= off) s += t;
    }
    if (lane == 31) ws[wid] = s;
    __syncthreads();
    if (wid == 0) {
        int t2 = (lane < 32) ? ws[lane] : 0;
        #pragma unroll
        for (int off = 1; off < 32; off <<= 1) {
            int t = __shfl_up_sync(0xffffffffu, t2, off);
            if (lane >= off) t2 += t;
        }
        ws[lane] = t2;
    }
    __syncthreads();
    int excl = s - v + (wid ? ws[wid - 1] : 0);
    if (i < n) g_rtmp[i] = excl;
    if (tid == 1023) g_bsum[b] = excl + v;
}
__global__ void scan2(int nb) {
    __shared__ int ws[4];
    int tid = threadIdx.x, lane = tid & 31, wid = tid >> 5;
    int v = (tid < nb) ? g_bsum[tid] : 0;
    int s = v;
    #pragma unroll
    for (int off = 1; off < 32; off <<= 1) {
        int t = __shfl_up_sync(0xffffffffu, s, off);
        if (lane >= off) s += t;
    }
    if (lane == 31) ws[wid] = s;
    __syncthreads();
    if (tid == 0) {
        int a = 0;
        #pragma unroll
        for (int q = 0; q < 4; q++) { int t = ws[q]; ws[q] = a; a += t; }
    }
    __syncthreads();
    int excl = s - v + ws[wid];
    if (tid < nb) g_bsum[tid] = excl;
}
// scan3 + invdeg fused
__global__ void scan3(int n) {
    int i = blockIdx.x * blockDim.x + threadIdx.x;
    if (i < n) {
        int deg = g_degi[i];
        int r = g_rtmp[i] + g_bsum[i >> 10];
        g_rowptr[i] = r;
        g_cursor[i] = r;
        g_invdeg[i] = 1.0f / fmaxf((float)deg, 1.0f);
        if (i == n - 1) g_rowptr[n] = r + deg;
    }
}
__global__ void fill_kernel(const int* __restrict__ src, const int* __restrict__ dst, int E, int n) {
    int i = blockIdx.x * blockDim.x + threadIdx.x;
    int stride = gridDim.x * blockDim.x;
    for (; i < E; i += stride) {
        int d = dst[i], s = src[i];
        if ((unsigned)d < (unsigned)n && (unsigned)s < (unsigned)n) {
            int slot = atomicAdd(&g_cursor[d], 1);
            if ((unsigned)slot < (unsigned)NE) g_adj[slot] = s;
        }
    }
}

// ---------------- prep: all 3 layers' fp16 weights in one kernel ----------------
__global__ void prep_w_all(const float* __restrict__ Wl0, const float* __restrict__ Wr0,
                           const float* __restrict__ Wl1, const float* __restrict__ Wr1,
                           const float* __restrict__ Wl2, const float* __restrict__ Wr2) {
    for (int i = blockIdx.x * blockDim.x + threadIdx.x; i < 262144; i += gridDim.x * blockDim.x) {
        float w;
        if (i < 65536) {            // L0: K=128, N=256, K2=256
            int n = i >> 8, k = i & 255;
            w = (k < 128) ? Wl0[(size_t)k * 256 + n] : Wr0[(size_t)(k - 128) * 256 + n];
        } else if (i < 196608) {    // L1: K=256, N=256, K2=512
            int j = i - 65536;
            int n = j >> 9, k = j & 511;
            w = (k < 256) ? Wl1[(size_t)k * 256 + n] : Wr1[(size_t)(k - 256) * 256 + n];
        } else {                    // L2 packed: rows 0-127 Wl2 cols, 128-255 Wr2 cols; K=256
            int j = i - 196608;
            int n = j >> 8, k = j & 255;
            w = (n < 128) ? Wl2[(size_t)k * 128 + n] : Wr2[(size_t)k * 128 + (n - 128)];
        }
        g_wf[i] = __float2half(w);
    }
}
__global__ void conv_x(const float* __restrict__ x, int total4) {
    for (int i = blockIdx.x * blockDim.x + threadIdx.x; i < total4; i += gridDim.x * blockDim.x) {
        float4 v = *(const float4*)(x + (size_t)i * 4);
        *(uint2*)(g_x16 + (size_t)i * 4) = make_uint2(packh2(v.x, v.y), packh2(v.z, v.w));
    }
}

// ---------------- mean aggregation: fp16 gather, fp32 accumulate, fp16 write ----------------
template <int D>
__global__ void __launch_bounds__(256) aggregate_kernel(int src_sel, int n) {
    const __half* feat = sel_h(src_sel);
    int w = (blockIdx.x * blockDim.x + threadIdx.x) >> 5;
    int lane = threadIdx.x & 31;
    if (w >= n) return;
    int j = g_rowptr[w], end = g_rowptr[w + 1];

    if (D == 256) {
        float acc[8] = {0.f, 0.f, 0.f, 0.f, 0.f, 0.f, 0.f, 0.f};
        for (; j + 3 < end; j += 4) {
            int s0 = g_adj[j], s1 = g_adj[j + 1], s2 = g_adj[j + 2], s3 = g_adj[j + 3];
            uint4 va = *(const uint4*)(feat + (size_t)s0 * 256 + lane * 8);
            uint4 vb = *(const uint4*)(feat + (size_t)s1 * 256 + lane * 8);
            uint4 vc = *(const uint4*)(feat + (size_t)s2 * 256 + lane * 8);
            uint4 vd = *(const uint4*)(feat + (size_t)s3 * 256 + lane * 8);
            hacc(va.x, acc[0], acc[1]); hacc(va.y, acc[2], acc[3]);
            hacc(va.z, acc[4], acc[5]); hacc(va.w, acc[6], acc[7]);
            hacc(vb.x, acc[0], acc[1]); hacc(vb.y, acc[2], acc[3]);
            hacc(vb.z, acc[4], acc[5]); hacc(vb.w, acc[6], acc[7]);
            hacc(vc.x, acc[0], acc[1]); hacc(vc.y, acc[2], acc[3]);
            hacc(vc.z, acc[4], acc[5]); hacc(vc.w, acc[6], acc[7]);
            hacc(vd.x, acc[0], acc[1]); hacc(vd.y, acc[2], acc[3]);
            hacc(vd.z, acc[4], acc[5]); hacc(vd.w, acc[6], acc[7]);
        }
        for (; j < end; j++) {
            int s0 = g_adj[j];
            uint4 va = *(const uint4*)(feat + (size_t)s0 * 256 + lane * 8);
            hacc(va.x, acc[0], acc[1]); hacc(va.y, acc[2], acc[3]);
            hacc(va.z, acc[4], acc[5]); hacc(va.w, acc[6], acc[7]);
        }
        float sc = g_invdeg[w];
        uint4 o;
        o.x = packh2(acc[0] * sc, acc[1] * sc);
        o.y = packh2(acc[2] * sc, acc[3] * sc);
        o.z = packh2(acc[4] * sc, acc[5] * sc);
        o.w = packh2(acc[6] * sc, acc[7] * sc);
        *(uint4*)(g_agg16 + (size_t)w * 256 + lane * 8) = o;
    } else {
        float acc[4] = {0.f, 0.f, 0.f, 0.f};
        for (; j + 3 < end; j += 4) {
            int s0 = g_adj[j], s1 = g_adj[j + 1], s2 = g_adj[j + 2], s3 = g_adj[j + 3];
            uint2 va = *(const uint2*)(feat + (size_t)s0 * 128 + lane * 4);
            uint2 vb = *(const uint2*)(feat + (size_t)s1 * 128 + lane * 4);
            uint2 vc = *(const uint2*)(feat + (size_t)s2 * 128 + lane * 4);
            uint2 vd = *(const uint2*)(feat + (size_t)s3 * 128 + lane * 4);
            hacc(va.x, acc[0], acc[1]); hacc(va.y, acc[2], acc[3]);
            hacc(vb.x, acc[0], acc[1]); hacc(vb.y, acc[2], acc[3]);
            hacc(vc.x, acc[0], acc[1]); hacc(vc.y, acc[2], acc[3]);
            hacc(vd.x, acc[0], acc[1]); hacc(vd.y, acc[2], acc[3]);
        }
        for (; j < end; j++) {
            int s0 = g_adj[j];
            uint2 va = *(const uint2*)(feat + (size_t)s0 * 128 + lane * 4);
            hacc(va.x, acc[0], acc[1]); hacc(va.y, acc[2], acc[3]);
        }
        float sc = g_invdeg[w];
        *(uint2*)(g_agg16 + (size_t)w * 128 + lane * 4) =
            make_uint2(packh2(acc[0] * sc, acc[1] * sc), packh2(acc[2] * sc, acc[3] * sc));
    }
}

// ---------------- final: out[w] += mean-gather of P (g_h116, D=128 fp16) ----------------
__global__ void __launch_bounds__(256) agg_add(float* __restrict__ out, int n) {
    int w = (blockIdx.x * blockDim.x + threadIdx.x) >> 5;
    int lane = threadIdx.x & 31;
    if (w >= n) return;
    int j = g_rowptr[w], end = g_rowptr[w + 1];
    float acc[4] = {0.f, 0.f, 0.f, 0.f};
    for (; j + 3 < end; j += 4) {
        int s0 = g_adj[j], s1 = g_adj[j + 1], s2 = g_adj[j + 2], s3 = g_adj[j + 3];
        uint2 va = *(const uint2*)(g_h116 + (size_t)s0 * 128 + lane * 4);
        uint2 vb = *(const uint2*)(g_h116 + (size_t)s1 * 128 + lane * 4);
        uint2 vc = *(const uint2*)(g_h116 + (size_t)s2 * 128 + lane * 4);
        uint2 vd = *(const uint2*)(g_h116 + (size_t)s3 * 128 + lane * 4);
        hacc(va.x, acc[0], acc[1]); hacc(va.y, acc[2], acc[3]);
        hacc(vb.x, acc[0], acc[1]); hacc(vb.y, acc[2], acc[3]);
        hacc(vc.x, acc[0], acc[1]); hacc(vc.y, acc[2], acc[3]);
        hacc(vd.x, acc[0], acc[1]); hacc(vd.y, acc[2], acc[3]);
    }
    for (; j < end; j++) {
        int s0 = g_adj[j];
        uint2 va = *(const uint2*)(g_h116 + (size_t)s0 * 128 + lane * 4);
        hacc(va.x, acc[0], acc[1]); hacc(va.y, acc[2], acc[3]);
    }
    float sc = g_invdeg[w];
    float4* op = (float4*)(out + (size_t)w * 128 + lane * 4);
    float4 cur = *op;
    cur.x += acc[0] * sc; cur.y += acc[1] * sc;
    cur.z += acc[2] * sc; cur.w += acc[3] * sc;
    *op = cur;
}

// ---------------- tensor-core GEMM (fp16, 3-stage cp.async ring, 1 sync/chunk) ----------------
// DUAL:  out = act([agg16 | Ax] @ W + b), A halves stride KA/2.
// !DUAL: out = Ax @ W (+b per OUTMODE), A stride KA.
// OUTMODE: 0 = fp32 out_ext (+bias), 1 = fp16 plane out_sel (+bias),
//          2 = split: blockIdx.y==0 -> P fp16 to g_h116 (no bias), ==1 -> fp32 out_ext (+bias)
template <int KA, int N, bool DUAL, bool RELU, int OUTMODE>
__global__ void __launch_bounds__(256) gemm_mma(
    int x_sel, const float* __restrict__ bias,
    float* __restrict__ out_ext, int out_sel, int wboff, int M) {
    extern __shared__ __align__(16) __half smp[];
    // layout: sA stage s @ s*5120, sB stage s @ 15360 + s*5120 (in halves)
    const uint32_t smb = smem_u32(smp);

    const __half* Ax = sel_h(x_sel);
    constexpr int ASTRIDE = DUAL ? KA / 2 : KA;
    constexpr int CHUNKS = KA / 32;

    int tid = threadIdx.x;
    int wid = tid >> 5, lane = tid & 31;
    int bm = blockIdx.x * 128, bn = blockIdx.y * 128;
    int wm = (wid & 3) * 32;
    int wn = (wid >> 2) * 64;

    float acc[2][8][4];
    #pragma unroll
    for (int i = 0; i < 2; i++)
        #pragma unroll
        for (int j = 0; j < 8; j++)
            #pragma unroll
            for (int q = 0; q < 4; q++) acc[i][j][q] = 0.f;

    int lr = tid >> 1, lc = (tid & 1) * 16;
    int arow = bm + lr; if (arow >= M) arow = M - 1;
    const __half* wb = g_wf + wboff;

    auto issue = [&](int c, int st) {
        int kk = c * 32;
        const __half* ap;
        if (DUAL) {
            constexpr int K = KA / 2;
            const __half* Asrc = (kk < K) ? g_agg16 : Ax;
            int col0 = (kk < K) ? kk : (kk - K);
            ap = Asrc + (size_t)arow * ASTRIDE + col0 + lc;
        } else {
            ap = Ax + (size_t)arow * ASTRIDE + kk + lc;
        }
        uint32_t abase = smb + (uint32_t)(st * 5120 + lr * 40 + lc) * 2;
        cp16(abase, ap);
        cp16(abase + 16, ap + 8);
        const __half* bp = wb + (size_t)(bn + lr) * KA + kk + lc;
        uint32_t bbase = smb + (uint32_t)(15360 + st * 5120 + lr * 40 + lc) * 2;
        cp16(bbase, bp);
        cp16(bbase + 16, bp + 8);
        CP_COMMIT();
    };

    issue(0, 0);
    issue(1, 1);

    #pragma unroll 1
    for (int c = 0; c < CHUNKS; c++) {
        int st = c % 3;
        cp_wait<1>();        // group c done; group c+1 may remain in flight
        __syncthreads();     // all threads' group-c data visible; stage (c+2)%3 free of readers
        if (c + 2 < CHUNKS) issue(c + 2, (c + 2) % 3);
        else CP_COMMIT();    // empty group keeps the wait<1> accounting exact

        uint32_t sa = smb + (uint32_t)(st * 5120) * 2;
        uint32_t sb = smb + (uint32_t)(15360 + st * 5120) * 2;
        #pragma unroll
        for (int ks = 0; ks < 2; ks++) {
            int lrow = lane & 15, lcolsel = (lane >> 4) * 8 + ks * 16;
            uint32_t a[2][4];
            #pragma unroll
            for (int mi = 0; mi < 2; mi++)
                ldmx4(a[mi], sa + (uint32_t)((wm + mi * 16 + lrow) * 40 + lcolsel) * 2);
            #pragma unroll
            for (int nj = 0; nj < 4; nj++) {
                uint32_t bf[4];
                ldmx4(bf, sb + (uint32_t)((wn + nj * 16 + lrow) * 40 + lcolsel) * 2);
                #pragma unroll
                for (int mi = 0; mi < 2; mi++) {
                    mma16816(acc[mi][nj * 2],     a[mi], bf[0], bf[2]);
                    mma16816(acc[mi][nj * 2 + 1], a[mi], bf[1], bf[3]);
                }
            }
        }
    }

    // ---- epilogue ----
    int tg = lane & 3, g = lane >> 2;
    __half* out16 = (out_sel == 1) ? g_h116 : g_h216;
    bool isP = (OUTMODE == 2) && (blockIdx.y == 0);
    #pragma unroll
    for (int mi = 0; mi < 2; mi++) {
        int r0 = bm + wm + mi * 16 + g;
        int r1 = r0 + 8;
        #pragma unroll
        for (int ni = 0; ni < 8; ni++) {
            int col = bn + wn + ni * 8 + tg * 2;
            int colb = (OUTMODE == 2) ? (col & 127) : col;
            float b0 = isP ? 0.f : __ldg(&bias[colb]);
            float b1 = isP ? 0.f : __ldg(&bias[colb + 1]);
            float v0 = acc[mi][ni][0] + b0, v1 = acc[mi][ni][1] + b1;
            float v2 = acc[mi][ni][2] + b0, v3 = acc[mi][ni][3] + b1;
            if (RELU) {
                v0 = fmaxf(v0, 0.f); v1 = fmaxf(v1, 0.f);
                v2 = fmaxf(v2, 0.f); v3 = fmaxf(v3, 0.f);
            }
            if (OUTMODE == 0) {
                if (r0 < M) *(float2*)(out_ext + (size_t)r0 * N + col) = make_float2(v0, v1);
                if (r1 < M) *(float2*)(out_ext + (size_t)r1 * N + col) = make_float2(v2, v3);
            } else if (OUTMODE == 1) {
                if (r0 < M) *(uint32_t*)(out16 + (size_t)r0 * N + col) = packh2(v0, v1);
                if (r1 < M) *(uint32_t*)(out16 + (size_t)r1 * N + col) = packh2(v2, v3);
            } else {
                if (isP) {  // P -> g_h116, stride 128, fp16, no bias
                    if (r0 < M) *(uint32_t*)(g_h116 + (size_t)r0 * 128 + colb) = packh2(v0, v1);
                    if (r1 < M) *(uint32_t*)(g_h116 + (size_t)r1 * 128 + colb) = packh2(v2, v3);
                } else {    // Q + b2 -> fp32 out, stride 128
                    if (r0 < M) *(float2*)(out_ext + (size_t)r0 * 128 + colb) = make_float2(v0, v1);
                    if (r1 < M) *(float2*)(out_ext + (size_t)r1 * 128 + colb) = make_float2(v2, v3);
                }
            }
        }
    }
}

// ---------------- launch ----------------
extern "C" void kernel_launch(void* const* d_in, const int* in_sizes, int n_in,
                              void* d_out, int out_size) {
    const float* x   = (const float*)d_in[0];
    const int*   ei  = (const int*)d_in[1];     // int32 edge_index [2, E]
    const float* Wl0 = (const float*)d_in[2];
    const float* b0  = (const float*)d_in[3];
    const float* Wr0 = (const float*)d_in[4];
    const float* Wl1 = (const float*)d_in[5];
    const float* b1  = (const float*)d_in[6];
    const float* Wr1 = (const float*)d_in[7];
    const float* Wl2 = (const float*)d_in[8];
    const float* b2  = (const float*)d_in[9];
    const float* Wr2 = (const float*)d_in[10];
    float* out = (float*)d_out;

    const int E = in_sizes[1] / 2;
    const int M = in_sizes[0] / 128;
    const int* src = ei;
    const int* dst = ei + E;
    const int nb = (M + 1023) / 1024;
    const int SMEM = 3 * 5120 * 2 * 2;   // 61440 bytes (3 stages x (A+B) x 5120 halves)

    cudaFuncSetAttribute(gemm_mma<256, 256, true, true, 1>,
                         cudaFuncAttributeMaxDynamicSharedMemorySize, SMEM);
    cudaFuncSetAttribute(gemm_mma<512, 256, true, true, 1>,
                         cudaFuncAttributeMaxDynamicSharedMemorySize, SMEM);
    cudaFuncSetAttribute(gemm_mma<256, 256, false, false, 2>,
                         cudaFuncAttributeMaxDynamicSharedMemorySize, SMEM);

    // --- CSR build (hierarchical scan; invdeg fused into scan3) ---
    zero_deg_kernel<<<(M + 255) / 256, 256>>>(M);
    hist_kernel<<<2048, 256>>>(dst, E, M);
    scan1<<<nb, 1024>>>(M);
    scan2<<<1, 128>>>(nb);
    scan3<<<(M + 255) / 256, 256>>>(M);
    fill_kernel<<<2048, 256>>>(src, dst, E, M);

    // --- prep: all fp16 weights in one kernel + fp16 x ---
    prep_w_all<<<1024, 256>>>(Wl0, Wr0, Wl1, Wr1, Wl2, Wr2);
    conv_x<<<2048, 256>>>(x, M * 32);

    const int agg_blocks = (M * 32 + 255) / 256;
    dim3 g2((M + 127) / 128, 2);

    // --- layer 0: 128 -> 256, relu ---
    aggregate_kernel<128><<<agg_blocks, 256>>>(0, M);
    gemm_mma<256, 256, true, true, 1><<<g2, 256, SMEM>>>(0, b0, nullptr, 1, 0, M);

    // --- layer 1: 256 -> 256, relu ---
    aggregate_kernel<256><<<agg_blocks, 256>>>(1, M);
    gemm_mma<512, 256, true, true, 1><<<g2, 256, SMEM>>>(1, b1, nullptr, 2, 65536, M);

    // --- layer 2 (commuted): [P|Q] = h2 @ [Wl2|Wr2]; out = Q + b2; out += mean-gather(P) ---
    gemm_mma<256, 256, false, false, 2><<<g2, 256, SMEM>>>(2, b2, out, 0, 196608, M);
    agg_add<<<agg_blocks, 256>>>(out, M);
}